// round 1
// baseline (speedup 1.0000x reference)
#include <cuda_runtime.h>
#include <cuda_bf16.h>

// ---------------- problem constants ----------------
#define BB 16
#define HH 32
#define WW 32
#define SS 1024          // H*W
#define C1 64
#define CO 88
#define CQKV 120
#define NHEAD 4
#define DH 10            // per-head dim
#define QSCALE 0.31622776601683794f  // 10^-0.5

// ---------------- scratch (static device globals; no allocation) ----------------
__device__ float g_h[BB * C1 * SS];          // conv1 out -> bn+relu in place
__device__ float g_bnstats[2 * C1];          // mean[64], istd[64]
__device__ float g_conv[BB * CO * SS];       // convo out
__device__ float g_qkv[BB * CQKV * SS];      // qkv out
__device__ float g_rw[64 * SS * 32];         // [bh][n][x'] rel-width logits
__device__ float g_rh[64 * SS * 32];         // [bh][n][y'] rel-height logits
__device__ float g_attn[BB * NHEAD * SS * DH]; // [b][h][n][d]  == [B][40][32][32] reinterpret
__device__ float g_attno[BB * 40 * SS];      // attno 1x1 out

// ---------------- kernel 1: conv1 3->64 3x3 SAME ----------------
__global__ void conv1_kernel(const float* __restrict__ x, const float* __restrict__ w,
                             const float* __restrict__ bias) {
    int oc = blockIdx.x;   // 0..63
    int b  = blockIdx.y;   // 0..15
    __shared__ float xs[3 * 34 * 34];
    __shared__ float ws[27];
    for (int i = threadIdx.x; i < 3 * 1156; i += blockDim.x) {
        int ic = i / 1156, r = i % 1156;
        int y = r / 34 - 1, xx = r % 34 - 1;
        float v = 0.f;
        if ((unsigned)y < 32u && (unsigned)xx < 32u)
            v = x[(b * 3 + ic) * SS + y * 32 + xx];
        xs[i] = v;
    }
    if (threadIdx.x < 27) ws[threadIdx.x] = w[oc * 27 + threadIdx.x];
    __syncthreads();
    float bb = bias[oc];
    for (int p = threadIdx.x; p < SS; p += blockDim.x) {
        int y = p >> 5, xx = p & 31;
        float acc = bb;
#pragma unroll
        for (int ic = 0; ic < 3; ic++)
#pragma unroll
            for (int ky = 0; ky < 3; ky++)
#pragma unroll
                for (int kx = 0; kx < 3; kx++)
                    acc += xs[ic * 1156 + (y + ky) * 34 + xx + kx] * ws[ic * 9 + ky * 3 + kx];
        g_h[(b * C1 + oc) * SS + p] = acc;
    }
}

// ---------------- kernel 2: BN batch statistics ----------------
__global__ void bn_stats_kernel() {
    int c = blockIdx.x;   // channel
    float s = 0.f, s2 = 0.f;
    for (int i = threadIdx.x; i < BB * SS; i += blockDim.x) {
        int b = i >> 10, p = i & 1023;
        float v = g_h[(b * C1 + c) * SS + p];
        s += v; s2 += v * v;
    }
    __shared__ float r1[256], r2[256];
    r1[threadIdx.x] = s; r2[threadIdx.x] = s2;
    __syncthreads();
    for (int o = 128; o > 0; o >>= 1) {
        if (threadIdx.x < o) { r1[threadIdx.x] += r1[threadIdx.x + o]; r2[threadIdx.x] += r2[threadIdx.x + o]; }
        __syncthreads();
    }
    if (threadIdx.x == 0) {
        float mu = r1[0] * (1.f / (BB * SS));
        float var = r2[0] * (1.f / (BB * SS)) - mu * mu;
        g_bnstats[c] = mu;
        g_bnstats[C1 + c] = rsqrtf(var + 1e-5f);
    }
}

// ---------------- kernel 3: BN apply + relu (in place) ----------------
__global__ void bn_apply_kernel(const float* __restrict__ gma, const float* __restrict__ bet) {
    int i = blockIdx.x * blockDim.x + threadIdx.x;   // 1M elems
    int c = (i >> 10) & 63;
    float v = (g_h[i] - g_bnstats[c]) * g_bnstats[C1 + c] * gma[c] + bet[c];
    g_h[i] = fmaxf(v, 0.f);
}

// ---------------- kernel 4: convo 64->88 3x3 SAME, 8-oc register blocking ----------------
#define ICCH 16
__global__ void convo_kernel(const float* __restrict__ w, const float* __restrict__ bias) {
    extern __shared__ float sm[];
    float* xs = sm;                     // ICCH * 1156
    float* ws = sm + ICCH * 1156;       // 8 * ICCH * 9
    int b = blockIdx.y;
    int oc0 = blockIdx.x * 8;
    int tid = threadIdx.x;              // 256
    float acc[8][4];
#pragma unroll
    for (int o = 0; o < 8; o++)
#pragma unroll
        for (int p4 = 0; p4 < 4; p4++) acc[o][p4] = 0.f;

    for (int icc = 0; icc < C1; icc += ICCH) {
        __syncthreads();
        for (int i = tid; i < ICCH * 1156; i += 256) {
            int ic = i / 1156, r = i % 1156;
            int y = r / 34 - 1, xx = r % 34 - 1;
            float v = 0.f;
            if ((unsigned)y < 32u && (unsigned)xx < 32u)
                v = g_h[(b * C1 + icc + ic) * SS + y * 32 + xx];
            xs[i] = v;
        }
        for (int i = tid; i < 8 * ICCH * 9; i += 256) {
            int o = i / (ICCH * 9), r = i % (ICCH * 9);
            int ic = r / 9, k = r % 9;
            ws[i] = w[((oc0 + o) * C1 + icc + ic) * 9 + k];
        }
        __syncthreads();
        for (int ic = 0; ic < ICCH; ic++) {
#pragma unroll
            for (int ky = 0; ky < 3; ky++)
#pragma unroll
                for (int kx = 0; kx < 3; kx++) {
                    float wr[8];
#pragma unroll
                    for (int o = 0; o < 8; o++) wr[o] = ws[o * ICCH * 9 + ic * 9 + ky * 3 + kx];
#pragma unroll
                    for (int p4 = 0; p4 < 4; p4++) {
                        int p = tid + p4 * 256;
                        int y = p >> 5, xx = p & 31;
                        float xv = xs[ic * 1156 + (y + ky) * 34 + xx + kx];
#pragma unroll
                        for (int o = 0; o < 8; o++) acc[o][p4] += xv * wr[o];
                    }
                }
        }
    }
#pragma unroll
    for (int o = 0; o < 8; o++) {
        float bb = bias[oc0 + o];
#pragma unroll
        for (int p4 = 0; p4 < 4; p4++) {
            int p = tid + p4 * 256;
            g_conv[(b * CO + oc0 + o) * SS + p] = acc[o][p4] + bb;
        }
    }
}

// ---------------- kernel 5: generic 1x1 conv (GEMM-ish), 8-oc blocking ----------------
__global__ void conv1x1_kernel(const float* __restrict__ in, const float* __restrict__ w,
                               const float* __restrict__ bias, float* __restrict__ out,
                               int IC, int OC) {
    extern __shared__ float xs[];       // 16 * 1024
    int b = blockIdx.y, oc0 = blockIdx.x * 8, tid = threadIdx.x;
    float acc[8][4];
#pragma unroll
    for (int o = 0; o < 8; o++)
#pragma unroll
        for (int p4 = 0; p4 < 4; p4++) acc[o][p4] = 0.f;
    for (int icc = 0; icc < IC; icc += 16) {
        int ch = min(16, IC - icc);
        __syncthreads();
        for (int i = tid; i < ch * SS; i += 256)
            xs[i] = in[(b * IC + icc + (i >> 10)) * SS + (i & 1023)];
        __syncthreads();
        for (int ic = 0; ic < ch; ic++) {
            float wr[8];
#pragma unroll
            for (int o = 0; o < 8; o++) wr[o] = w[(oc0 + o) * IC + icc + ic];
#pragma unroll
            for (int p4 = 0; p4 < 4; p4++) {
                float xv = xs[ic * SS + tid + p4 * 256];
#pragma unroll
                for (int o = 0; o < 8; o++) acc[o][p4] += xv * wr[o];
            }
        }
    }
#pragma unroll
    for (int o = 0; o < 8; o++) {
        float bb = bias[oc0 + o];
#pragma unroll
        for (int p4 = 0; p4 < 4; p4++)
            out[(b * OC + oc0 + o) * SS + tid + p4 * 256] = acc[o][p4] + bb;
    }
}

// ---------------- kernel 6: relative-position logits precompute ----------------
// RW[bh][n][x'] = sum_d q_scaled[d]*relw[x'-x+31][d],   x = n%32
// RH[bh][n][y'] = sum_d q_scaled[d]*relh[y'-y+31][d],   y = n/32
__global__ void relpos_kernel(const float* __restrict__ relh, const float* __restrict__ relw) {
    int bh = blockIdx.x;               // 0..63
    int b = bh >> 2, hh = bh & 3;
    __shared__ float sh[63 * DH], sw[63 * DH];
    for (int i = threadIdx.x; i < 630; i += blockDim.x) { sh[i] = relh[i]; sw[i] = relw[i]; }
    __syncthreads();
    for (int n = threadIdx.x; n < SS; n += blockDim.x) {
        float q[DH];
#pragma unroll
        for (int d = 0; d < DH; d++)
            q[d] = g_qkv[(b * CQKV + hh * DH + d) * SS + n] * QSCALE;
        int y = n >> 5, x = n & 31;
        for (int t = 0; t < 32; t++) {
            const float* pw = &sw[(t - x + 31) * DH];
            const float* ph = &sh[(t - y + 31) * DH];
            float aw = 0.f, ah = 0.f;
#pragma unroll
            for (int d = 0; d < DH; d++) { aw += q[d] * pw[d]; ah += q[d] * ph[d]; }
            g_rw[(bh * SS + n) * 32 + t] = aw;
            g_rh[(bh * SS + n) * 32 + t] = ah;
        }
    }
}

// ---------------- kernel 7: fused attention (QK^T + rel logits + softmax + PV) ----------------
// grid (4 query-tiles, 64 bh), 256 threads; one query per thread, streaming over 1024 keys.
// No-max softmax: logits are O(0.2) for this problem's input scales — exp is exact-safe.
__global__ void attn_kernel() {
    extern __shared__ float sm[];
    float* Kt  = sm;                    // [1024][12] (10 + 2 pad)
    float* Vt  = sm + SS * 12;          // [1024][12]
    float* rws = Vt + SS * 12;          // [256][33]
    float* rhs = rws + 256 * 33;        // [256][33]
    int bh = blockIdx.y, qt = blockIdx.x, tid = threadIdx.x;
    int b = bh >> 2, hh = bh & 3;
    const float* kbase = &g_qkv[(b * CQKV + 40 + hh * DH) * SS];
    const float* vbase = &g_qkv[(b * CQKV + 80 + hh * DH) * SS];
#pragma unroll
    for (int d = 0; d < DH; d++)
        for (int m = tid; m < SS; m += 256) {
            Kt[m * 12 + d] = kbase[d * SS + m];
            Vt[m * 12 + d] = vbase[d * SS + m];
        }
    for (int m = tid; m < SS; m += 256) {
        Kt[m * 12 + 10] = 0.f; Kt[m * 12 + 11] = 0.f;
        Vt[m * 12 + 10] = 0.f; Vt[m * 12 + 11] = 0.f;
    }
    int n0 = qt * 256;
    for (int i = tid; i < 256 * 32; i += 256) {
        int qq = i >> 5, t = i & 31;
        rws[qq * 33 + t] = g_rw[(bh * SS + n0 + qq) * 32 + t];
        rhs[qq * 33 + t] = g_rh[(bh * SS + n0 + qq) * 32 + t];
    }
    __syncthreads();

    int n = n0 + tid;
    const float* qbase = &g_qkv[(b * CQKV + hh * DH) * SS];
    float q[DH];
#pragma unroll
    for (int d = 0; d < DH; d++) q[d] = qbase[d * SS + n] * QSCALE;

    float ssum = 0.f;
    float acc[DH];
#pragma unroll
    for (int d = 0; d < DH; d++) acc[d] = 0.f;
    const float* rwr = &rws[tid * 33];
    const float* rhr = &rhs[tid * 33];

#pragma unroll 4
    for (int m = 0; m < SS; m++) {
        const float4* kp = (const float4*)&Kt[m * 12];
        float4 k0 = kp[0], k1 = kp[1], k2 = kp[2];
        float l = q[0] * k0.x + q[1] * k0.y + q[2] * k0.z + q[3] * k0.w
                + q[4] * k1.x + q[5] * k1.y + q[6] * k1.z + q[7] * k1.w
                + q[8] * k2.x + q[9] * k2.y;
        l += rwr[m & 31] + rhr[m >> 5];
        float p = __expf(l);
        ssum += p;
        const float4* vp = (const float4*)&Vt[m * 12];
        float4 v0 = vp[0], v1 = vp[1], v2 = vp[2];
        acc[0] += p * v0.x; acc[1] += p * v0.y; acc[2] += p * v0.z; acc[3] += p * v0.w;
        acc[4] += p * v1.x; acc[5] += p * v1.y; acc[6] += p * v1.z; acc[7] += p * v1.w;
        acc[8] += p * v2.x; acc[9] += p * v2.y;
    }
    float inv = 1.f / ssum;
#pragma unroll
    for (int d = 0; d < DH; d++)
        g_attn[(bh * SS + n) * DH + d] = acc[d] * inv;
}

// ---------------- kernel 8: global avg pool + fc ----------------
__global__ void pool_fc_kernel(const float* __restrict__ fcw, const float* __restrict__ fcb,
                               float* __restrict__ out) {
    int b = blockIdx.x;
    int tid = threadIdx.x;             // 128
    int warp = tid >> 5, lane = tid & 31;
    __shared__ float pooled[128];
    for (int c = warp; c < 128; c += 4) {
        const float* src = (c < CO) ? &g_conv[(b * CO + c) * SS]
                                    : &g_attno[(b * 40 + c - CO) * SS];
        float s = 0.f;
        for (int i = lane; i < SS; i += 32) s += src[i];
#pragma unroll
        for (int o = 16; o; o >>= 1) s += __shfl_xor_sync(0xffffffffu, s, o);
        if (lane == 0) pooled[c] = s * (1.f / SS);
    }
    __syncthreads();
    if (tid < 100) {
        float a = fcb[tid];
        for (int c = 0; c < 128; c++) a += pooled[c] * fcw[tid * 128 + c];
        out[b * 100 + tid] = a;
    }
}

// ---------------- host launch ----------------
extern "C" void kernel_launch(void* const* d_in, const int* in_sizes, int n_in,
                              void* d_out, int out_size) {
    const float* x        = (const float*)d_in[0];
    const float* conv1_w  = (const float*)d_in[1];
    const float* conv1_b  = (const float*)d_in[2];
    const float* bn1_g    = (const float*)d_in[3];
    const float* bn1_b    = (const float*)d_in[4];
    const float* convo_w  = (const float*)d_in[5];
    const float* convo_b  = (const float*)d_in[6];
    const float* qkv_w    = (const float*)d_in[7];
    const float* qkv_b    = (const float*)d_in[8];
    const float* attno_w  = (const float*)d_in[9];
    const float* attno_b  = (const float*)d_in[10];
    const float* key_rel_h = (const float*)d_in[11];
    const float* key_rel_w = (const float*)d_in[12];
    const float* fc_w     = (const float*)d_in[13];
    const float* fc_b     = (const float*)d_in[14];
    float* out = (float*)d_out;

    const int CONVO_SMEM = (ICCH * 1156 + 8 * ICCH * 9) * 4;       // 78592
    const int C1X1_SMEM  = 16 * SS * 4;                            // 65536
    const int ATTN_SMEM  = (SS * 12 * 2 + 256 * 33 * 2) * 4;       // 165888
    cudaFuncSetAttribute(convo_kernel, cudaFuncAttributeMaxDynamicSharedMemorySize, CONVO_SMEM);
    cudaFuncSetAttribute(conv1x1_kernel, cudaFuncAttributeMaxDynamicSharedMemorySize, C1X1_SMEM);
    cudaFuncSetAttribute(attn_kernel, cudaFuncAttributeMaxDynamicSharedMemorySize, ATTN_SMEM);

    conv1_kernel<<<dim3(C1, BB), 256>>>(x, conv1_w, conv1_b);
    bn_stats_kernel<<<C1, 256>>>();
    bn_apply_kernel<<<1024, 1024>>>(bn1_g, bn1_b);
    convo_kernel<<<dim3(CO / 8, BB), 256, CONVO_SMEM>>>(convo_w, convo_b);

    float* d_qkv; cudaGetSymbolAddress((void**)&d_qkv, g_qkv);
    float* d_attn; cudaGetSymbolAddress((void**)&d_attn, g_attn);
    float* d_attno; cudaGetSymbolAddress((void**)&d_attno, g_attno);
    float* d_h; cudaGetSymbolAddress((void**)&d_h, g_h);

    conv1x1_kernel<<<dim3(CQKV / 8, BB), 256, C1X1_SMEM>>>(d_h, qkv_w, qkv_b, d_qkv, C1, CQKV);
    relpos_kernel<<<64, 256>>>(key_rel_h, key_rel_w);
    attn_kernel<<<dim3(4, 64), 256, ATTN_SMEM>>>();
    conv1x1_kernel<<<dim3(40 / 8, BB), 256, C1X1_SMEM>>>(d_attn, attno_w, attno_b, d_attno, 40, 40);
    pool_fc_kernel<<<BB, 128>>>(fc_w, fc_b, out);
}

// round 2
// speedup vs baseline: 1.3635x; 1.3635x over previous
#include <cuda_runtime.h>
#include <cuda_bf16.h>

#define BB 16
#define SS 1024
#define C1 64
#define CO 88
#define DH 10
#define QSCALE 0.31622776601683794f

typedef unsigned long long ull;

__device__ __forceinline__ void fma2(ull& d, ull a, ull b) {
    asm("fma.rn.f32x2 %0, %1, %2, %0;" : "+l"(d) : "l"(a), "l"(b));
}
__device__ __forceinline__ ull pk(float a, float b) {
    ull r; asm("mov.b64 %0, {%1, %2};" : "=l"(r) : "f"(a), "f"(b)); return r;
}
__device__ __forceinline__ float2 up(ull v) {
    float2 r; asm("mov.b64 {%0, %1}, %2;" : "=f"(r.x), "=f"(r.y) : "l"(v)); return r;
}

// ---------------- scratch ----------------
__device__ float g_h[BB * C1 * SS];
__device__ float g_part[BB * C1 * 2];
__device__ float g_bn[2 * C1];              // scale[64], shift[64]
__device__ float g_conv[BB * CO * SS];
__device__ float g_qkv[BB * 120 * SS];
__device__ float g_attn[BB * 4 * SS * DH];  // [bh][n][d] == [B][40][32][32] reinterp
__device__ float g_attno[BB * 40 * SS];

// ---------------- conv1 3->64 3x3 + per-block BN partial stats ----------------
__global__ void conv1_kernel(const float* __restrict__ x, const float* __restrict__ w,
                             const float* __restrict__ bias) {
    int oc = blockIdx.x, b = blockIdx.y;
    __shared__ float xs[3 * 34 * 34];
    __shared__ float ws[27];
    __shared__ float sred[16];
    int tid = threadIdx.x;
    for (int i = tid; i < 3 * 1156; i += 256) {
        int ic = i / 1156, r = i % 1156;
        int y = r / 34 - 1, xx = r % 34 - 1;
        float v = 0.f;
        if ((unsigned)y < 32u && (unsigned)xx < 32u)
            v = x[(b * 3 + ic) * SS + y * 32 + xx];
        xs[i] = v;
    }
    if (tid < 27) ws[tid] = w[oc * 27 + tid];
    __syncthreads();
    float bb = bias[oc];
    float s = 0.f, s2 = 0.f;
    for (int p = tid; p < SS; p += 256) {
        int y = p >> 5, xx = p & 31;
        float acc = bb;
#pragma unroll
        for (int ic = 0; ic < 3; ic++)
#pragma unroll
            for (int ky = 0; ky < 3; ky++)
#pragma unroll
                for (int kx = 0; kx < 3; kx++)
                    acc += xs[ic * 1156 + (y + ky) * 34 + xx + kx] * ws[ic * 9 + ky * 3 + kx];
        g_h[(b * C1 + oc) * SS + p] = acc;
        s += acc; s2 += acc * acc;
    }
#pragma unroll
    for (int o = 16; o; o >>= 1) {
        s  += __shfl_xor_sync(0xffffffffu, s, o);
        s2 += __shfl_xor_sync(0xffffffffu, s2, o);
    }
    if ((tid & 31) == 0) { sred[tid >> 5] = s; sred[8 + (tid >> 5)] = s2; }
    __syncthreads();
    if (tid == 0) {
        float S = 0.f, S2 = 0.f;
        for (int i = 0; i < 8; i++) { S += sred[i]; S2 += sred[8 + i]; }
        g_part[(b * 64 + oc) * 2]     = S;
        g_part[(b * 64 + oc) * 2 + 1] = S2;
    }
}

// ---------------- BN finalize: per-channel scale/shift ----------------
__global__ void bn_finalize_kernel(const float* __restrict__ gma, const float* __restrict__ bet) {
    int c = threadIdx.x;
    if (c < 64) {
        float S = 0.f, S2 = 0.f;
        for (int b = 0; b < 16; b++) {
            S  += g_part[(b * 64 + c) * 2];
            S2 += g_part[(b * 64 + c) * 2 + 1];
        }
        float mu  = S * (1.f / 16384.f);
        float var = S2 * (1.f / 16384.f) - mu * mu;
        float istd = rsqrtf(var + 1e-5f);
        float sc = gma[c] * istd;
        g_bn[c] = sc;
        g_bn[64 + c] = bet[c] - mu * sc;
    }
}

// ---------------- convo 64->88 3x3, f32x2, BN+relu applied on load ----------------
// grid (11, 16, 2halves), 128 threads, 4 adjacent px + 8 oc per thread
__global__ void convo_kernel(const float* __restrict__ w, const float* __restrict__ bias) {
    extern __shared__ float sm[];
    float* xs = sm;                          // [16][18][36]
    ull* wsd = (ull*)(sm + 16 * 18 * 36);    // [8][16][9] duplicated pairs
    int b = blockIdx.y, half = blockIdx.z, oc0 = blockIdx.x * 8;
    int tid = threadIdx.x;
    int r = tid >> 3, x0 = (tid & 7) * 4;
    ull acc[8][2];
#pragma unroll
    for (int o = 0; o < 8; o++) { acc[o][0] = 0ull; acc[o][1] = 0ull; }

    for (int icc = 0; icc < 64; icc += 16) {
        __syncthreads();
        for (int i = tid; i < 16 * 18 * 36; i += 128) {
            int ic = i / 648, rem = i % 648, tr = rem / 36, tc = rem % 36;
            int iy = half * 16 + tr - 1, ix = tc - 1;
            float v = 0.f;
            if ((unsigned)iy < 32u && (unsigned)ix < 32u) {
                int icg = icc + ic;
                v = g_h[(b * 64 + icg) * SS + iy * 32 + ix];
                v = fmaxf(v * g_bn[icg] + g_bn[64 + icg], 0.f);
            }
            xs[i] = v;
        }
        for (int i = tid; i < 8 * 16 * 9; i += 128) {
            int o = i / 144, rem = i % 144, ic = rem / 9, k = rem % 9;
            float wv = w[((oc0 + o) * 64 + icc + ic) * 9 + k];
            wsd[i] = pk(wv, wv);
        }
        __syncthreads();
        for (int ic = 0; ic < 16; ic++) {
#pragma unroll
            for (int ky = 0; ky < 3; ky++) {
                const ull* xp = (const ull*)(xs + (ic * 18 + r + ky) * 36 + x0);
                ull e0 = xp[0], e1 = xp[1], e2 = xp[2];
                float2 f0 = up(e0), f1 = up(e1), f2 = up(e2);
                ull m0 = pk(f0.y, f1.x), m1 = pk(f1.y, f2.x);
#pragma unroll
                for (int o = 0; o < 8; o++) {
                    ull w0 = wsd[(o * 16 + ic) * 9 + ky * 3 + 0];
                    fma2(acc[o][0], w0, e0); fma2(acc[o][1], w0, e1);
                }
#pragma unroll
                for (int o = 0; o < 8; o++) {
                    ull w1 = wsd[(o * 16 + ic) * 9 + ky * 3 + 1];
                    fma2(acc[o][0], w1, m0); fma2(acc[o][1], w1, m1);
                }
#pragma unroll
                for (int o = 0; o < 8; o++) {
                    ull w2 = wsd[(o * 16 + ic) * 9 + ky * 3 + 2];
                    fma2(acc[o][0], w2, e1); fma2(acc[o][1], w2, e2);
                }
            }
        }
    }
    int p = half * 512 + r * 32 + x0;
#pragma unroll
    for (int o = 0; o < 8; o++) {
        float bb = bias[oc0 + o];
        float2 a = up(acc[o][0]), c = up(acc[o][1]);
        float4 v = { a.x + bb, a.y + bb, c.x + bb, c.y + bb };
        *(float4*)&g_conv[(b * 88 + oc0 + o) * SS + p] = v;
    }
}

// ---------------- 1x1 conv (f32x2), optional fused BN+relu on input ----------------
// grid (OC/8, 16), 256 threads, 4 adjacent px + 8 oc per thread
__global__ void conv1x1_kernel(const float* __restrict__ in, const float* __restrict__ w,
                               const float* __restrict__ bias, float* __restrict__ out,
                               int IC, int OC, int useBN) {
    extern __shared__ float sm[];
    float* xs = sm;                         // [16][1024]
    ull* wsd = (ull*)(sm + 16 * 1024);      // [8][16]
    int b = blockIdx.y, oc0 = blockIdx.x * 8, tid = threadIdx.x;
    ull acc[8][2];
#pragma unroll
    for (int o = 0; o < 8; o++) { acc[o][0] = 0ull; acc[o][1] = 0ull; }
    for (int icc = 0; icc < IC; icc += 16) {
        int ch = min(16, IC - icc);
        __syncthreads();
        for (int i = tid; i < ch * 1024; i += 256) {
            int ic = i >> 10, p = i & 1023;
            float v = in[(b * IC + icc + ic) * SS + p];
            if (useBN) v = fmaxf(v * g_bn[icc + ic] + g_bn[64 + icc + ic], 0.f);
            xs[i] = v;
        }
        for (int i = tid; i < 8 * ch; i += 256) {
            int o = i / ch, ic = i % ch;
            float wv = w[(oc0 + o) * IC + icc + ic];
            wsd[o * 16 + ic] = pk(wv, wv);
        }
        __syncthreads();
        for (int ic = 0; ic < ch; ic++) {
            const ull* xp = (const ull*)(xs + ic * 1024 + tid * 4);
            ull xa = xp[0], xb = xp[1];
#pragma unroll
            for (int o = 0; o < 8; o++) {
                ull wv = wsd[o * 16 + ic];
                fma2(acc[o][0], wv, xa); fma2(acc[o][1], wv, xb);
            }
        }
    }
#pragma unroll
    for (int o = 0; o < 8; o++) {
        float bb = bias[oc0 + o];
        float2 a = up(acc[o][0]), c = up(acc[o][1]);
        float4 v = { a.x + bb, a.y + bb, c.x + bb, c.y + bb };
        *(float4*)&out[(b * OC + oc0 + o) * SS + tid * 4] = v;
    }
}

// ---------------- fused attention: rel-logits + QK^T + softmax + PV ----------------
// grid (2, 64bh), 256 threads; each thread owns queries n0=qt*512+tid, n1=n0+256.
// f32x2 packed over head dims. Shift-free softmax (logits O(0.2) for this problem).
__global__ void attn_kernel(const float* __restrict__ relh, const float* __restrict__ relw) {
    extern __shared__ float sm[];
    float* Kt  = sm;                    // [1024][10]
    float* Vt  = Kt + 10240;            // [1024][10]
    float* rwp = Vt + 10240;            // float2[256][33]
    float* rhp = rwp + 256 * 66;        // float2[256][33]
    float* shs = rhp + 256 * 66;        // [63][10]
    float* sws = shs + 630;             // [63][10]
    int qt = blockIdx.x, bh = blockIdx.y, tid = threadIdx.x;
    int b = bh >> 2, hh = bh & 3;
    const float* qbase = g_qkv + (b * 120 + hh * 10) * SS;
    const float* kbase = qbase + 40 * SS;
    const float* vbase = qbase + 80 * SS;

    for (int i = tid; i < 630; i += 256) { shs[i] = relh[i]; sws[i] = relw[i]; }
#pragma unroll
    for (int d = 0; d < 10; d++)
        for (int m = tid; m < 1024; m += 256) {
            Kt[m * 10 + d] = kbase[d * SS + m];
            Vt[m * 10 + d] = vbase[d * SS + m];
        }
    int n0 = qt * 512 + tid, n1 = n0 + 256;
    ull q0p[5], q1p[5];
#pragma unroll
    for (int j = 0; j < 5; j++) {
        q0p[j] = pk(qbase[(2 * j) * SS + n0] * QSCALE, qbase[(2 * j + 1) * SS + n0] * QSCALE);
        q1p[j] = pk(qbase[(2 * j) * SS + n1] * QSCALE, qbase[(2 * j + 1) * SS + n1] * QSCALE);
    }
    __syncthreads();

    // rel logit rows (thread-private smem rows; no further sync needed)
    int x0 = n0 & 31, y0 = n0 >> 5, y1 = y0 + 8;
    float2* rwr = (float2*)rwp + tid * 33;
    float2* rhr = (float2*)rhp + tid * 33;
    for (int t = 0; t < 32; t++) {
        const ull* swr  = (const ull*)(sws + (t - x0 + 31) * 10);
        const ull* shr0 = (const ull*)(shs + (t - y0 + 31) * 10);
        const ull* shr1 = (const ull*)(shs + (t - y1 + 31) * 10);
        ull dw0 = 0, dw1 = 0, dh0 = 0, dh1 = 0;
#pragma unroll
        for (int j = 0; j < 5; j++) {
            ull sv = swr[j];
            fma2(dw0, q0p[j], sv); fma2(dw1, q1p[j], sv);
            fma2(dh0, q0p[j], shr0[j]); fma2(dh1, q1p[j], shr1[j]);
        }
        float2 a = up(dw0), c = up(dw1);
        rwr[t] = make_float2(a.x + a.y, c.x + c.y);
        float2 e = up(dh0), f = up(dh1);
        rhr[t] = make_float2(e.x + e.y, f.x + f.y);
    }

    ull acc0[5], acc1[5];
#pragma unroll
    for (int j = 0; j < 5; j++) { acc0[j] = 0ull; acc1[j] = 0ull; }
    float s0 = 0.f, s1 = 0.f;
    const ull* kr = (const ull*)Kt;
    const ull* vr = (const ull*)Vt;
    for (int my = 0; my < 32; my++) {
        float2 rh = rhr[my];
#pragma unroll 8
        for (int mx = 0; mx < 32; mx++) {
            ull k0 = kr[0], k1 = kr[1], k2 = kr[2], k3 = kr[3], k4 = kr[4]; kr += 5;
            ull d0 = 0, d1 = 0;
            fma2(d0, q0p[0], k0); fma2(d1, q1p[0], k0);
            fma2(d0, q0p[1], k1); fma2(d1, q1p[1], k1);
            fma2(d0, q0p[2], k2); fma2(d1, q1p[2], k2);
            fma2(d0, q0p[3], k3); fma2(d1, q1p[3], k3);
            fma2(d0, q0p[4], k4); fma2(d1, q1p[4], k4);
            float2 u0 = up(d0), u1 = up(d1), rw = rwr[mx];
            float l0 = (u0.x + u0.y) + (rw.x + rh.x);
            float l1 = (u1.x + u1.y) + (rw.y + rh.y);
            float p0 = __expf(l0), p1 = __expf(l1);
            s0 += p0; s1 += p1;
            ull pp0 = pk(p0, p0), pp1 = pk(p1, p1);
            ull v0 = vr[0], v1 = vr[1], v2 = vr[2], v3 = vr[3], v4 = vr[4]; vr += 5;
            fma2(acc0[0], pp0, v0); fma2(acc1[0], pp1, v0);
            fma2(acc0[1], pp0, v1); fma2(acc1[1], pp1, v1);
            fma2(acc0[2], pp0, v2); fma2(acc1[2], pp1, v2);
            fma2(acc0[3], pp0, v3); fma2(acc1[3], pp1, v3);
            fma2(acc0[4], pp0, v4); fma2(acc1[4], pp1, v4);
        }
    }
    float i0 = 1.f / s0, i1 = 1.f / s1;
    float2* o0 = (float2*)(g_attn + (bh * SS + n0) * 10);
    float2* o1 = (float2*)(g_attn + (bh * SS + n1) * 10);
#pragma unroll
    for (int j = 0; j < 5; j++) {
        float2 a = up(acc0[j]); o0[j] = make_float2(a.x * i0, a.y * i0);
        float2 c = up(acc1[j]); o1[j] = make_float2(c.x * i1, c.y * i1);
    }
}

// ---------------- global avg pool + fc ----------------
__global__ void pool_fc_kernel(const float* __restrict__ fcw, const float* __restrict__ fcb,
                               float* __restrict__ out) {
    int b = blockIdx.x;
    int tid = threadIdx.x;
    int warp = tid >> 5, lane = tid & 31;
    __shared__ float pooled[128];
    for (int c = warp; c < 128; c += 4) {
        const float* src = (c < CO) ? &g_conv[(b * CO + c) * SS]
                                    : &g_attno[(b * 40 + c - CO) * SS];
        float s = 0.f;
        for (int i = lane; i < SS; i += 32) s += src[i];
#pragma unroll
        for (int o = 16; o; o >>= 1) s += __shfl_xor_sync(0xffffffffu, s, o);
        if (lane == 0) pooled[c] = s * (1.f / SS);
    }
    __syncthreads();
    if (tid < 100) {
        float a = fcb[tid];
        for (int c = 0; c < 128; c++) a += pooled[c] * fcw[tid * 128 + c];
        out[b * 100 + tid] = a;
    }
}

// ---------------- host ----------------
extern "C" void kernel_launch(void* const* d_in, const int* in_sizes, int n_in,
                              void* d_out, int out_size) {
    const float* x        = (const float*)d_in[0];
    const float* conv1_w  = (const float*)d_in[1];
    const float* conv1_b  = (const float*)d_in[2];
    const float* bn1_g    = (const float*)d_in[3];
    const float* bn1_b    = (const float*)d_in[4];
    const float* convo_w  = (const float*)d_in[5];
    const float* convo_b  = (const float*)d_in[6];
    const float* qkv_w    = (const float*)d_in[7];
    const float* qkv_b    = (const float*)d_in[8];
    const float* attno_w  = (const float*)d_in[9];
    const float* attno_b  = (const float*)d_in[10];
    const float* key_rel_h = (const float*)d_in[11];
    const float* key_rel_w = (const float*)d_in[12];
    const float* fc_w     = (const float*)d_in[13];
    const float* fc_b     = (const float*)d_in[14];
    float* out = (float*)d_out;

    const int CONVO_SMEM = (16 * 18 * 36) * 4 + 8 * 16 * 9 * 8;            // 50688
    const int C1X1_SMEM  = 16 * 1024 * 4 + 8 * 16 * 8;                     // 66560
    const int ATTN_SMEM  = (10240 * 2 + 256 * 66 * 2 + 630 * 2) * 4;       // 222128
    cudaFuncSetAttribute(convo_kernel, cudaFuncAttributeMaxDynamicSharedMemorySize, CONVO_SMEM);
    cudaFuncSetAttribute(conv1x1_kernel, cudaFuncAttributeMaxDynamicSharedMemorySize, C1X1_SMEM);
    cudaFuncSetAttribute(attn_kernel, cudaFuncAttributeMaxDynamicSharedMemorySize, ATTN_SMEM);

    float* d_h;    cudaGetSymbolAddress((void**)&d_h, g_h);
    float* d_qkv;  cudaGetSymbolAddress((void**)&d_qkv, g_qkv);
    float* d_attn; cudaGetSymbolAddress((void**)&d_attn, g_attn);
    float* d_attno; cudaGetSymbolAddress((void**)&d_attno, g_attno);

    conv1_kernel<<<dim3(C1, BB), 256>>>(x, conv1_w, conv1_b);
    bn_finalize_kernel<<<1, 64>>>(bn1_g, bn1_b);
    convo_kernel<<<dim3(11, BB, 2), 128, CONVO_SMEM>>>(convo_w, convo_b);
    conv1x1_kernel<<<dim3(15, BB), 256, C1X1_SMEM>>>(d_h, qkv_w, qkv_b, d_qkv, 64, 120, 1);
    attn_kernel<<<dim3(2, 64), 256, ATTN_SMEM>>>(key_rel_h, key_rel_w);
    conv1x1_kernel<<<dim3(5, BB), 256, C1X1_SMEM>>>(d_attn, attno_w, attno_b, d_attno, 40, 40, 0);
    pool_fc_kernel<<<BB, 128>>>(fc_w, fc_b, out);
}

// round 3
// speedup vs baseline: 1.6069x; 1.1785x over previous
#include <cuda_runtime.h>
#include <cuda_bf16.h>

#define BB 16
#define SS 1024
#define C1 64
#define CO 88
#define DH 10
#define QSCALE 0.31622776601683794f
#define L2E 1.4426950408889634f
#define SCL (QSCALE * L2E)

typedef unsigned long long ull;
typedef unsigned int uint32;

__device__ __forceinline__ void fma2(ull& d, ull a, ull b) {
    asm("fma.rn.f32x2 %0, %1, %2, %0;" : "+l"(d) : "l"(a), "l"(b));
}
__device__ __forceinline__ ull pk(float a, float b) {
    ull r; asm("mov.b64 %0, {%1, %2};" : "=l"(r) : "f"(a), "f"(b)); return r;
}
__device__ __forceinline__ float2 up(ull v) {
    float2 r; asm("mov.b64 {%0, %1}, %2;" : "=f"(r.x), "=f"(r.y) : "l"(v)); return r;
}
__device__ __forceinline__ float ex2f(float x) {
    float r; asm("ex2.approx.ftz.f32 %0, %1;" : "=f"(r) : "f"(x)); return r;
}
// pack {hi, lo} floats -> bf16x2 (lo in low half)
__device__ __forceinline__ uint32 pkbf(float hi, float lo) {
    uint32 r; asm("cvt.rn.bf16x2.f32 %0, %1, %2;" : "=r"(r) : "f"(hi), "f"(lo)); return r;
}
#define MMA16(d, a, b) asm volatile( \
    "mma.sync.aligned.m16n8k16.row.col.f32.bf16.bf16.f32 " \
    "{%0,%1,%2,%3}, {%4,%5,%6,%7}, {%8,%9}, {%0,%1,%2,%3};\n" \
    : "+f"(d[0]), "+f"(d[1]), "+f"(d[2]), "+f"(d[3]) \
    : "r"(a[0]), "r"(a[1]), "r"(a[2]), "r"(a[3]), "r"(b[0]), "r"(b[1]))

// ---------------- scratch ----------------
__device__ float g_h[BB * C1 * SS];
__device__ float g_part[BB * C1 * 2];
__device__ float g_bn[2 * C1];
__device__ float g_conv[BB * CO * SS];
__device__ float g_qkv[BB * 120 * SS];
__device__ float g_attn[BB * 4 * SS * DH];   // [bh][n][d] == [B][40][32][32]
__device__ float g_attno[BB * 40 * SS];

// ---------------- conv1 3->64 3x3 + BN partial stats ----------------
__global__ void conv1_kernel(const float* __restrict__ x, const float* __restrict__ w,
                             const float* __restrict__ bias) {
    int oc = blockIdx.x, b = blockIdx.y;
    __shared__ float xs[3 * 34 * 34];
    __shared__ float ws[27];
    __shared__ float sred[16];
    int tid = threadIdx.x;
    for (int i = tid; i < 3 * 1156; i += 256) {
        int ic = i / 1156, r = i % 1156;
        int y = r / 34 - 1, xx = r % 34 - 1;
        float v = 0.f;
        if ((unsigned)y < 32u && (unsigned)xx < 32u)
            v = x[(b * 3 + ic) * SS + y * 32 + xx];
        xs[i] = v;
    }
    if (tid < 27) ws[tid] = w[oc * 27 + tid];
    __syncthreads();
    float bb = bias[oc];
    float s = 0.f, s2 = 0.f;
    for (int p = tid; p < SS; p += 256) {
        int y = p >> 5, xx = p & 31;
        float acc = bb;
#pragma unroll
        for (int ic = 0; ic < 3; ic++)
#pragma unroll
            for (int ky = 0; ky < 3; ky++)
#pragma unroll
                for (int kx = 0; kx < 3; kx++)
                    acc += xs[ic * 1156 + (y + ky) * 34 + xx + kx] * ws[ic * 9 + ky * 3 + kx];
        g_h[(b * C1 + oc) * SS + p] = acc;
        s += acc; s2 += acc * acc;
    }
#pragma unroll
    for (int o = 16; o; o >>= 1) {
        s  += __shfl_xor_sync(0xffffffffu, s, o);
        s2 += __shfl_xor_sync(0xffffffffu, s2, o);
    }
    if ((tid & 31) == 0) { sred[tid >> 5] = s; sred[8 + (tid >> 5)] = s2; }
    __syncthreads();
    if (tid == 0) {
        float S = 0.f, S2 = 0.f;
        for (int i = 0; i < 8; i++) { S += sred[i]; S2 += sred[8 + i]; }
        g_part[(b * 64 + oc) * 2]     = S;
        g_part[(b * 64 + oc) * 2 + 1] = S2;
    }
}

__global__ void bn_finalize_kernel(const float* __restrict__ gma, const float* __restrict__ bet) {
    int c = threadIdx.x;
    if (c < 64) {
        float S = 0.f, S2 = 0.f;
        for (int b = 0; b < 16; b++) {
            S  += g_part[(b * 64 + c) * 2];
            S2 += g_part[(b * 64 + c) * 2 + 1];
        }
        float mu  = S * (1.f / 16384.f);
        float var = S2 * (1.f / 16384.f) - mu * mu;
        float istd = rsqrtf(var + 1e-5f);
        float sc = gma[c] * istd;
        g_bn[c] = sc;
        g_bn[64 + c] = bet[c] - mu * sc;
    }
}

// ---------------- convo 64->88 3x3 (f32x2), BN+relu on load ----------------
__global__ void convo_kernel(const float* __restrict__ w, const float* __restrict__ bias) {
    extern __shared__ float sm[];
    float* xs = sm;                          // [16][18][36]
    ull* wsd = (ull*)(sm + 16 * 18 * 36);    // [8][16][9]
    int b = blockIdx.y, half = blockIdx.z, oc0 = blockIdx.x * 8;
    int tid = threadIdx.x;
    int r = tid >> 3, x0 = (tid & 7) * 4;
    ull acc[8][2];
#pragma unroll
    for (int o = 0; o < 8; o++) { acc[o][0] = 0ull; acc[o][1] = 0ull; }

    for (int icc = 0; icc < 64; icc += 16) {
        __syncthreads();
        for (int i = tid; i < 16 * 18 * 36; i += 128) {
            int ic = i / 648, rem = i % 648, tr = rem / 36, tc = rem % 36;
            int iy = half * 16 + tr - 1, ix = tc - 1;
            float v = 0.f;
            if ((unsigned)iy < 32u && (unsigned)ix < 32u) {
                int icg = icc + ic;
                v = g_h[(b * 64 + icg) * SS + iy * 32 + ix];
                v = fmaxf(v * g_bn[icg] + g_bn[64 + icg], 0.f);
            }
            xs[i] = v;
        }
        for (int i = tid; i < 8 * 16 * 9; i += 128) {
            int o = i / 144, rem = i % 144, ic = rem / 9, k = rem % 9;
            float wv = w[((oc0 + o) * 64 + icc + ic) * 9 + k];
            wsd[i] = pk(wv, wv);
        }
        __syncthreads();
        for (int ic = 0; ic < 16; ic++) {
#pragma unroll
            for (int ky = 0; ky < 3; ky++) {
                const ull* xp = (const ull*)(xs + (ic * 18 + r + ky) * 36 + x0);
                ull e0 = xp[0], e1 = xp[1], e2 = xp[2];
                float2 f0 = up(e0), f1 = up(e1), f2 = up(e2);
                ull m0 = pk(f0.y, f1.x), m1 = pk(f1.y, f2.x);
#pragma unroll
                for (int o = 0; o < 8; o++) {
                    ull w0 = wsd[(o * 16 + ic) * 9 + ky * 3 + 0];
                    fma2(acc[o][0], w0, e0); fma2(acc[o][1], w0, e1);
                }
#pragma unroll
                for (int o = 0; o < 8; o++) {
                    ull w1 = wsd[(o * 16 + ic) * 9 + ky * 3 + 1];
                    fma2(acc[o][0], w1, m0); fma2(acc[o][1], w1, m1);
                }
#pragma unroll
                for (int o = 0; o < 8; o++) {
                    ull w2 = wsd[(o * 16 + ic) * 9 + ky * 3 + 2];
                    fma2(acc[o][0], w2, e1); fma2(acc[o][1], w2, e2);
                }
            }
        }
    }
    int p = half * 512 + r * 32 + x0;
#pragma unroll
    for (int o = 0; o < 8; o++) {
        float bb = bias[oc0 + o];
        float2 a = up(acc[o][0]), c = up(acc[o][1]);
        float4 v = { a.x + bb, a.y + bb, c.x + bb, c.y + bb };
        *(float4*)&g_conv[(b * 88 + oc0 + o) * SS + p] = v;
    }
}

// ---------------- 1x1 conv: zero-sync L2 streaming ----------------
// grid (OC/8, 16), 256 threads, 4 px/thread, 8 oc/block, weights in smem once.
__global__ void __launch_bounds__(256) conv1x1_kernel(
        const float* __restrict__ in, const float* __restrict__ w,
        const float* __restrict__ bias, float* __restrict__ out,
        int IC, int OC, int useBN) {
    __shared__ ull ws[8 * 64];
    __shared__ float sc[64], sh[64];
    int b = blockIdx.y, oc0 = blockIdx.x * 8, tid = threadIdx.x;
    for (int i = tid; i < 8 * IC; i += 256) {
        int o = i / IC, ic = i % IC;
        float wv = w[(oc0 + o) * IC + ic];
        ws[o * 64 + ic] = pk(wv, wv);
    }
    if (useBN)
        for (int i = tid; i < IC; i += 256) { sc[i] = g_bn[i]; sh[i] = g_bn[64 + i]; }
    __syncthreads();

    const float* ip = in + (size_t)b * IC * SS + tid * 4;
    ull acc[8][2];
#pragma unroll
    for (int o = 0; o < 8; o++) { acc[o][0] = 0ull; acc[o][1] = 0ull; }
#pragma unroll 4
    for (int ic = 0; ic < IC; ic++) {
        float4 v = *(const float4*)(ip + ic * SS);
        if (useBN) {
            v.x = fmaxf(v.x * sc[ic] + sh[ic], 0.f);
            v.y = fmaxf(v.y * sc[ic] + sh[ic], 0.f);
            v.z = fmaxf(v.z * sc[ic] + sh[ic], 0.f);
            v.w = fmaxf(v.w * sc[ic] + sh[ic], 0.f);
        }
        ull xa = pk(v.x, v.y), xb = pk(v.z, v.w);
#pragma unroll
        for (int o = 0; o < 8; o++) {
            ull wv = ws[o * 64 + ic];
            fma2(acc[o][0], wv, xa); fma2(acc[o][1], wv, xb);
        }
    }
#pragma unroll
    for (int o = 0; o < 8; o++) {
        float bb = bias[oc0 + o];
        float2 a = up(acc[o][0]), c = up(acc[o][1]);
        float4 v = { a.x + bb, a.y + bb, c.x + bb, c.y + bb };
        *(float4*)&out[(size_t)(b * OC + oc0 + o) * SS + tid * 4] = v;
    }
}

// ---------------- fused attention: bf16 mma.sync flash-style ----------------
// grid (4 qtiles, 64 bh), 256 threads (8 warps); warp owns 32 queries.
// smem: K[1024][18]bf16, V^T[16][1032]bf16, Q[256][18]bf16 (pre-scaled by QSCALE*log2e),
//       rw[256][34]f32, rh[256][34]f32, rel source tables.
#define SM_K   0
#define SM_V   36864
#define SM_Q   (36864 + 33024)
#define SM_RW  (SM_Q + 9216)
#define SM_RH  (SM_RW + 34816)
#define SM_REL (SM_RH + 34816)
#define ATTN_SMEM (SM_REL + 5040)

__global__ void __launch_bounds__(256) attn_kernel(const float* __restrict__ relh,
                                                   const float* __restrict__ relw) {
    extern __shared__ char smem[];
    __nv_bfloat16* Ksm = (__nv_bfloat16*)(smem + SM_K);   // [1024][18]
    __nv_bfloat16* Qsm = (__nv_bfloat16*)(smem + SM_Q);   // [256][18]
    uint32* K32 = (uint32*)(smem + SM_K);
    uint32* V32 = (uint32*)(smem + SM_V);                 // [16][516] uint (bf16x2 pairs)
    uint32* Q32 = (uint32*)(smem + SM_Q);
    float* rw   = (float*)(smem + SM_RW);                 // [256][34]
    float* rh   = (float*)(smem + SM_RH);                 // [256][34]
    float* srel = (float*)(smem + SM_REL);                // relh[630], relw[630]

    int qt = blockIdx.x, bh = blockIdx.y;
    int b = bh >> 2, hh = bh & 3;
    const float* qb = g_qkv + (b * 120 + hh * 10) * SS;
    const float* kb = qb + 40 * SS;
    const float* vb = qb + 80 * SS;
    int tid = threadIdx.x;

    for (int i = tid; i < 1260; i += 256) srel[i] = (i < 630 ? relh[i] : relw[i - 630]);
    // K staging: [m][d] bf16, rows padded to 18
#pragma unroll
    for (int d = 0; d < 10; d++)
        for (int m = tid; m < 1024; m += 256)
            Ksm[m * 18 + d] = __float2bfloat16(kb[d * SS + m]);
    for (int m = tid; m < 1024; m += 256) {
        K32[m * 9 + 5] = 0; K32[m * 9 + 6] = 0; K32[m * 9 + 7] = 0; K32[m * 9 + 8] = 0;
    }
    // V^T staging: [d][key] bf16 rows padded to 1032 (pack key pairs)
#pragma unroll
    for (int d = 0; d < 10; d++)
        for (int i = tid; i < 512; i += 256) {
            float2 v = *(const float2*)(vb + d * SS + 2 * i);
            V32[d * 516 + i] = pkbf(v.y, v.x);
        }
    for (int d = 10; d < 16; d++)
        for (int i = tid; i < 516; i += 256) V32[d * 516 + i] = 0;
    // Q staging (scaled)
    {
        int q = tid;
#pragma unroll
        for (int d = 0; d < 10; d++)
            Qsm[q * 18 + d] = __float2bfloat16(qb[d * SS + qt * 256 + q] * SCL);
        Q32[q * 9 + 5] = 0; Q32[q * 9 + 6] = 0; Q32[q * 9 + 7] = 0; Q32[q * 9 + 8] = 0;
    }
    __syncthreads();

    // rel tables (thread owns block-local query q = tid)
    {
        int n = qt * 256 + tid;
        float qv[10];
#pragma unroll
        for (int d = 0; d < 10; d++) qv[d] = qb[d * SS + n] * SCL;
        int x = n & 31, y = n >> 5;
        for (int t = 0; t < 32; t++) {
            const float* pw = srel + 630 + (t - x + 31) * 10;
            const float* ph = srel + (t - y + 31) * 10;
            float aw = 0.f, ah = 0.f;
#pragma unroll
            for (int d = 0; d < 10; d++) { aw += qv[d] * pw[d]; ah += qv[d] * ph[d]; }
            rw[tid * 34 + t] = aw;
            rh[tid * 34 + t] = ah;
        }
    }
    __syncthreads();

    int lane = tid & 31, wz = tid >> 5;
    int g = lane >> 2, t = lane & 3;
    // Q A-fragments (2 m-tiles of 16 rows)
    uint32 qa[2][4];
#pragma unroll
    for (int mt = 0; mt < 2; mt++) {
        int r0 = wz * 32 + mt * 16;
        qa[mt][0] = Q32[(r0 + g) * 9 + t];
        qa[mt][1] = Q32[(r0 + g + 8) * 9 + t];
        qa[mt][2] = Q32[(r0 + g) * 9 + t + 4];
        qa[mt][3] = Q32[(r0 + g + 8) * 9 + t + 4];
    }
    float O[2][2][4];
    float s[4];
#pragma unroll
    for (int i = 0; i < 4; i++) {
        s[i] = 0.f;
        O[0][0][i] = 0.f; O[0][1][i] = 0.f; O[1][0][i] = 0.f; O[1][1][i] = 0.f;
    }

    for (int ch = 0; ch < 64; ch++) {
        int my = ch >> 1, mx0 = (ch & 1) << 4;
        int k0 = my * 32 + mx0;
        uint32 kb0[2], kb1[2], vb0[2], vb1[2];
        kb0[0] = K32[(k0 + g) * 9 + t];      kb0[1] = K32[(k0 + g) * 9 + t + 4];
        kb1[0] = K32[(k0 + 8 + g) * 9 + t];  kb1[1] = K32[(k0 + 8 + g) * 9 + t + 4];
        int kh = k0 >> 1;
        vb0[0] = V32[g * 516 + kh + t];        vb0[1] = V32[g * 516 + kh + t + 4];
        vb1[0] = V32[(g + 8) * 516 + kh + t];  vb1[1] = V32[(g + 8) * 516 + kh + t + 4];
#pragma unroll
        for (int mt = 0; mt < 2; mt++) {
            float c0[4] = {0.f, 0.f, 0.f, 0.f}, c1[4] = {0.f, 0.f, 0.f, 0.f};
            MMA16(c0, qa[mt], kb0);
            MMA16(c1, qa[mt], kb1);
            int r0 = wz * 32 + mt * 16 + g;
            float rh0 = rh[r0 * 34 + my], rh1 = rh[(r0 + 8) * 34 + my];
            float2 rw00 = *(float2*)&rw[r0 * 34 + mx0 + 2 * t];
            float2 rw01 = *(float2*)&rw[r0 * 34 + mx0 + 8 + 2 * t];
            float2 rw10 = *(float2*)&rw[(r0 + 8) * 34 + mx0 + 2 * t];
            float2 rw11 = *(float2*)&rw[(r0 + 8) * 34 + mx0 + 8 + 2 * t];
            float p00 = ex2f(c0[0] + rw00.x + rh0);
            float p01 = ex2f(c0[1] + rw00.y + rh0);
            float p02 = ex2f(c0[2] + rw10.x + rh1);
            float p03 = ex2f(c0[3] + rw10.y + rh1);
            float p10 = ex2f(c1[0] + rw01.x + rh0);
            float p11 = ex2f(c1[1] + rw01.y + rh0);
            float p12 = ex2f(c1[2] + rw11.x + rh1);
            float p13 = ex2f(c1[3] + rw11.y + rh1);
            s[mt * 2]     += (p00 + p01) + (p10 + p11);
            s[mt * 2 + 1] += (p02 + p03) + (p12 + p13);
            uint32 pa[4];
            pa[0] = pkbf(p01, p00);
            pa[1] = pkbf(p03, p02);
            pa[2] = pkbf(p11, p10);
            pa[3] = pkbf(p13, p12);
            MMA16(O[mt][0], pa, vb0);
            MMA16(O[mt][1], pa, vb1);
        }
    }
#pragma unroll
    for (int j = 0; j < 4; j++) {
        s[j] += __shfl_xor_sync(0xffffffffu, s[j], 1);
        s[j] += __shfl_xor_sync(0xffffffffu, s[j], 2);
        s[j] = 1.f / s[j];
    }
#pragma unroll
    for (int mt = 0; mt < 2; mt++) {
        int q0 = qt * 256 + wz * 32 + mt * 16 + g;
        float* op = g_attn + ((size_t)bh * 1024 + q0) * 10;
        float i0 = s[mt * 2], i1 = s[mt * 2 + 1];
        *(float2*)(op + 2 * t)      = make_float2(O[mt][0][0] * i0, O[mt][0][1] * i0);
        *(float2*)(op + 80 + 2 * t) = make_float2(O[mt][0][2] * i1, O[mt][0][3] * i1);
        if (t == 0) {
            *(float2*)(op + 8)      = make_float2(O[mt][1][0] * i0, O[mt][1][1] * i0);
            *(float2*)(op + 80 + 8) = make_float2(O[mt][1][2] * i1, O[mt][1][3] * i1);
        }
    }
}

// ---------------- global avg pool + fc ----------------
__global__ void pool_fc_kernel(const float* __restrict__ fcw, const float* __restrict__ fcb,
                               float* __restrict__ out) {
    int b = blockIdx.x;
    int tid = threadIdx.x;
    int warp = tid >> 5, lane = tid & 31;
    __shared__ float pooled[128];
    for (int c = warp; c < 128; c += 4) {
        const float* src = (c < CO) ? &g_conv[(b * CO + c) * SS]
                                    : &g_attno[(b * 40 + c - CO) * SS];
        float s = 0.f;
        for (int i = lane; i < SS; i += 32) s += src[i];
#pragma unroll
        for (int o = 16; o; o >>= 1) s += __shfl_xor_sync(0xffffffffu, s, o);
        if (lane == 0) pooled[c] = s * (1.f / SS);
    }
    __syncthreads();
    if (tid < 100) {
        float a = fcb[tid];
        for (int c = 0; c < 128; c++) a += pooled[c] * fcw[tid * 128 + c];
        out[b * 100 + tid] = a;
    }
}

// ---------------- host ----------------
extern "C" void kernel_launch(void* const* d_in, const int* in_sizes, int n_in,
                              void* d_out, int out_size) {
    const float* x        = (const float*)d_in[0];
    const float* conv1_w  = (const float*)d_in[1];
    const float* conv1_b  = (const float*)d_in[2];
    const float* bn1_g    = (const float*)d_in[3];
    const float* bn1_b    = (const float*)d_in[4];
    const float* convo_w  = (const float*)d_in[5];
    const float* convo_b  = (const float*)d_in[6];
    const float* qkv_w    = (const float*)d_in[7];
    const float* qkv_b    = (const float*)d_in[8];
    const float* attno_w  = (const float*)d_in[9];
    const float* attno_b  = (const float*)d_in[10];
    const float* key_rel_h = (const float*)d_in[11];
    const float* key_rel_w = (const float*)d_in[12];
    const float* fc_w     = (const float*)d_in[13];
    const float* fc_b     = (const float*)d_in[14];
    float* out = (float*)d_out;

    const int CONVO_SMEM = (16 * 18 * 36) * 4 + 8 * 16 * 9 * 8;   // 50688
    cudaFuncSetAttribute(convo_kernel, cudaFuncAttributeMaxDynamicSharedMemorySize, CONVO_SMEM);
    cudaFuncSetAttribute(attn_kernel, cudaFuncAttributeMaxDynamicSharedMemorySize, ATTN_SMEM);

    float* d_h;    cudaGetSymbolAddress((void**)&d_h, g_h);
    float* d_qkv;  cudaGetSymbolAddress((void**)&d_qkv, g_qkv);
    float* d_attn; cudaGetSymbolAddress((void**)&d_attn, g_attn);
    float* d_attno; cudaGetSymbolAddress((void**)&d_attno, g_attno);

    conv1_kernel<<<dim3(C1, BB), 256>>>(x, conv1_w, conv1_b);
    bn_finalize_kernel<<<1, 64>>>(bn1_g, bn1_b);
    convo_kernel<<<dim3(11, BB, 2), 128, CONVO_SMEM>>>(convo_w, convo_b);
    conv1x1_kernel<<<dim3(15, BB), 256>>>(d_h, qkv_w, qkv_b, d_qkv, 64, 120, 1);
    attn_kernel<<<dim3(4, 64), 256, ATTN_SMEM>>>(key_rel_h, key_rel_w);
    conv1x1_kernel<<<dim3(5, BB), 256>>>(d_attn, attno_w, attno_b, d_attno, 40, 40, 0);
    pool_fc_kernel<<<BB, 128>>>(fc_w, fc_b, out);
}

// round 4
// speedup vs baseline: 2.0419x; 1.2707x over previous
#include <cuda_runtime.h>
#include <cuda_bf16.h>

#define BB 16
#define SS 1024
#define C1 64
#define CO 88
#define DH 10
#define QSCALE 0.31622776601683794f
#define L2E 1.4426950408889634f
#define SCL (QSCALE * L2E)

typedef unsigned long long ull;
typedef unsigned int uint32;

__device__ __forceinline__ void fma2(ull& d, ull a, ull b) {
    asm("fma.rn.f32x2 %0, %1, %2, %0;" : "+l"(d) : "l"(a), "l"(b));
}
__device__ __forceinline__ ull pk(float a, float b) {
    ull r; asm("mov.b64 %0, {%1, %2};" : "=l"(r) : "f"(a), "f"(b)); return r;
}
__device__ __forceinline__ float2 up(ull v) {
    float2 r; asm("mov.b64 {%0, %1}, %2;" : "=f"(r.x), "=f"(r.y) : "l"(v)); return r;
}
__device__ __forceinline__ float ex2f(float x) {
    float r; asm("ex2.approx.ftz.f32 %0, %1;" : "=f"(r) : "f"(x)); return r;
}
__device__ __forceinline__ uint32 pkbf(float hi, float lo) {
    uint32 r; asm("cvt.rn.bf16x2.f32 %0, %1, %2;" : "=r"(r) : "f"(hi), "f"(lo)); return r;
}
#define MMA16(d, a, b) asm volatile( \
    "mma.sync.aligned.m16n8k16.row.col.f32.bf16.bf16.f32 " \
    "{%0,%1,%2,%3}, {%4,%5,%6,%7}, {%8,%9}, {%0,%1,%2,%3};\n" \
    : "+f"(d[0]), "+f"(d[1]), "+f"(d[2]), "+f"(d[3]) \
    : "r"(a[0]), "r"(a[1]), "r"(a[2]), "r"(a[3]), "r"(b[0]), "r"(b[1]))

// ---------------- scratch ----------------
__device__ float g_h[BB * C1 * SS];
__device__ float g_part[BB * C1 * 2];
__device__ float g_bn[2 * C1];
__device__ float g_conv[BB * CO * SS];
__device__ float g_qkv[BB * 120 * SS];
__device__ float g_attn[BB * 4 * SS * DH];
__device__ float g_attno[BB * 40 * SS];
__device__ float g_pool[BB * 128];

// ---------------- conv1 3->64 3x3 + BN partial stats ----------------
__global__ void conv1_kernel(const float* __restrict__ x, const float* __restrict__ w,
                             const float* __restrict__ bias) {
    int oc = blockIdx.x, b = blockIdx.y;
    __shared__ float xs[3 * 34 * 34];
    __shared__ float ws[27];
    __shared__ float sred[16];
    int tid = threadIdx.x;
    for (int i = tid; i < 3 * 1156; i += 256) {
        int ic = i / 1156, r = i % 1156;
        int y = r / 34 - 1, xx = r % 34 - 1;
        float v = 0.f;
        if ((unsigned)y < 32u && (unsigned)xx < 32u)
            v = x[(b * 3 + ic) * SS + y * 32 + xx];
        xs[i] = v;
    }
    if (tid < 27) ws[tid] = w[oc * 27 + tid];
    __syncthreads();
    float bb = bias[oc];
    float s = 0.f, s2 = 0.f;
    for (int p = tid; p < SS; p += 256) {
        int y = p >> 5, xx = p & 31;
        float acc = bb;
#pragma unroll
        for (int ic = 0; ic < 3; ic++)
#pragma unroll
            for (int ky = 0; ky < 3; ky++)
#pragma unroll
                for (int kx = 0; kx < 3; kx++)
                    acc += xs[ic * 1156 + (y + ky) * 34 + xx + kx] * ws[ic * 9 + ky * 3 + kx];
        g_h[(b * C1 + oc) * SS + p] = acc;
        s += acc; s2 += acc * acc;
    }
#pragma unroll
    for (int o = 16; o; o >>= 1) {
        s  += __shfl_xor_sync(0xffffffffu, s, o);
        s2 += __shfl_xor_sync(0xffffffffu, s2, o);
    }
    if ((tid & 31) == 0) { sred[tid >> 5] = s; sred[8 + (tid >> 5)] = s2; }
    __syncthreads();
    if (tid == 0) {
        float S = 0.f, S2 = 0.f;
        for (int i = 0; i < 8; i++) { S += sred[i]; S2 += sred[8 + i]; }
        g_part[(b * 64 + oc) * 2]     = S;
        g_part[(b * 64 + oc) * 2 + 1] = S2;
    }
}

__global__ void bn_finalize_kernel(const float* __restrict__ gma, const float* __restrict__ bet) {
    int c = threadIdx.x;
    if (c < 64) {
        float S = 0.f, S2 = 0.f;
        for (int b = 0; b < 16; b++) {
            S  += g_part[(b * 64 + c) * 2];
            S2 += g_part[(b * 64 + c) * 2 + 1];
        }
        float mu  = S * (1.f / 16384.f);
        float var = S2 * (1.f / 16384.f) - mu * mu;
        float istd = rsqrtf(var + 1e-5f);
        float sc = gma[c] * istd;
        g_bn[c] = sc;
        g_bn[64 + c] = bet[c] - mu * sc;
    }
}

// ---------------- convo 64->88 3x3 (f32x2), BN+relu on load ----------------
__global__ void convo_kernel(const float* __restrict__ w, const float* __restrict__ bias) {
    extern __shared__ float sm[];
    float* xs = sm;                          // [16][18][36]
    ull* wsd = (ull*)(sm + 16 * 18 * 36);    // [8][16][9]
    int b = blockIdx.y, half = blockIdx.z, oc0 = blockIdx.x * 8;
    int tid = threadIdx.x;
    int r = tid >> 3, x0 = (tid & 7) * 4;
    ull acc[8][2];
#pragma unroll
    for (int o = 0; o < 8; o++) { acc[o][0] = 0ull; acc[o][1] = 0ull; }

    for (int icc = 0; icc < 64; icc += 16) {
        __syncthreads();
        for (int i = tid; i < 16 * 18 * 36; i += 128) {
            int ic = i / 648, rem = i % 648, tr = rem / 36, tc = rem % 36;
            int iy = half * 16 + tr - 1, ix = tc - 1;
            float v = 0.f;
            if ((unsigned)iy < 32u && (unsigned)ix < 32u) {
                int icg = icc + ic;
                v = g_h[(b * 64 + icg) * SS + iy * 32 + ix];
                v = fmaxf(v * g_bn[icg] + g_bn[64 + icg], 0.f);
            }
            xs[i] = v;
        }
        for (int i = tid; i < 8 * 16 * 9; i += 128) {
            int o = i / 144, rem = i % 144, ic = rem / 9, k = rem % 9;
            float wv = w[((oc0 + o) * 64 + icc + ic) * 9 + k];
            wsd[i] = pk(wv, wv);
        }
        __syncthreads();
        for (int ic = 0; ic < 16; ic++) {
#pragma unroll
            for (int ky = 0; ky < 3; ky++) {
                const ull* xp = (const ull*)(xs + (ic * 18 + r + ky) * 36 + x0);
                ull e0 = xp[0], e1 = xp[1], e2 = xp[2];
                float2 f0 = up(e0), f1 = up(e1), f2 = up(e2);
                ull m0 = pk(f0.y, f1.x), m1 = pk(f1.y, f2.x);
#pragma unroll
                for (int o = 0; o < 8; o++) {
                    ull w0 = wsd[(o * 16 + ic) * 9 + ky * 3 + 0];
                    fma2(acc[o][0], w0, e0); fma2(acc[o][1], w0, e1);
                }
#pragma unroll
                for (int o = 0; o < 8; o++) {
                    ull w1 = wsd[(o * 16 + ic) * 9 + ky * 3 + 1];
                    fma2(acc[o][0], w1, m0); fma2(acc[o][1], w1, m1);
                }
#pragma unroll
                for (int o = 0; o < 8; o++) {
                    ull w2 = wsd[(o * 16 + ic) * 9 + ky * 3 + 2];
                    fma2(acc[o][0], w2, e1); fma2(acc[o][1], w2, e2);
                }
            }
        }
    }
    int p = half * 512 + r * 32 + x0;
#pragma unroll
    for (int o = 0; o < 8; o++) {
        float bb = bias[oc0 + o];
        float2 a = up(acc[o][0]), c = up(acc[o][1]);
        float4 v = { a.x + bb, a.y + bb, c.x + bb, c.y + bb };
        *(float4*)&g_conv[(b * 88 + oc0 + o) * SS + p] = v;
    }
}

// ---------------- 1x1 conv: zero-sync L2 streaming, 2px/thread ----------------
// grid (OC/8, B, 2), 256 threads
__global__ void __launch_bounds__(256) conv1x1_kernel(
        const float* __restrict__ in, const float* __restrict__ w,
        const float* __restrict__ bias, float* __restrict__ out,
        int IC, int OC, int useBN) {
    __shared__ ull ws[8 * 64];
    __shared__ float sc[64], sh[64];
    int b = blockIdx.y, oc0 = blockIdx.x * 8, half = blockIdx.z, tid = threadIdx.x;
    for (int i = tid; i < 8 * IC; i += 256) {
        int o = i / IC, ic = i % IC;
        float wv = w[(oc0 + o) * IC + ic];
        ws[o * 64 + ic] = pk(wv, wv);
    }
    if (useBN)
        for (int i = tid; i < IC; i += 256) { sc[i] = g_bn[i]; sh[i] = g_bn[64 + i]; }
    __syncthreads();

    const float* ip = in + (size_t)b * IC * SS + half * 512 + tid * 2;
    ull acc[8];
#pragma unroll
    for (int o = 0; o < 8; o++) acc[o] = 0ull;
#pragma unroll 8
    for (int ic = 0; ic < IC; ic++) {
        float2 v = *(const float2*)(ip + ic * SS);
        if (useBN) {
            v.x = fmaxf(v.x * sc[ic] + sh[ic], 0.f);
            v.y = fmaxf(v.y * sc[ic] + sh[ic], 0.f);
        }
        ull xa = pk(v.x, v.y);
#pragma unroll
        for (int o = 0; o < 8; o++) fma2(acc[o], ws[o * 64 + ic], xa);
    }
#pragma unroll
    for (int o = 0; o < 8; o++) {
        float bb = bias[oc0 + o];
        float2 a = up(acc[o]);
        *(float2*)&out[(size_t)(b * OC + oc0 + o) * SS + half * 512 + tid * 2]
            = make_float2(a.x + bb, a.y + bb);
    }
}

// ---------------- fused attention: bf16 mma.sync flash-style ----------------
#define SM_K   0
#define SM_V   36864
#define SM_Q   (36864 + 33024)
#define SM_RW  (SM_Q + 9216)
#define SM_RH  (SM_RW + 34816)
#define SM_REL (SM_RH + 34816)
#define ATTN_SMEM (SM_REL + 5040)

__global__ void __launch_bounds__(256) attn_kernel(const float* __restrict__ relh,
                                                   const float* __restrict__ relw) {
    extern __shared__ char smem[];
    __nv_bfloat16* Ksm = (__nv_bfloat16*)(smem + SM_K);   // [1024][18]
    __nv_bfloat16* Qsm = (__nv_bfloat16*)(smem + SM_Q);   // [256][18]
    uint32* K32 = (uint32*)(smem + SM_K);
    uint32* V32 = (uint32*)(smem + SM_V);                 // [16][516]
    uint32* Q32 = (uint32*)(smem + SM_Q);
    float* rw   = (float*)(smem + SM_RW);                 // [256][34]
    float* rh   = (float*)(smem + SM_RH);                 // [256][34]
    float* srel = (float*)(smem + SM_REL);

    int qt = blockIdx.x, bh = blockIdx.y;
    int b = bh >> 2, hh = bh & 3;
    const float* qb = g_qkv + (b * 120 + hh * 10) * SS;
    const float* kb = qb + 40 * SS;
    const float* vb = qb + 80 * SS;
    int tid = threadIdx.x;

    for (int i = tid; i < 1260; i += 256) srel[i] = (i < 630 ? relh[i] : relw[i - 630]);
#pragma unroll
    for (int d = 0; d < 10; d++)
        for (int m = tid; m < 1024; m += 256)
            Ksm[m * 18 + d] = __float2bfloat16(kb[d * SS + m]);
    for (int m = tid; m < 1024; m += 256) {
        K32[m * 9 + 5] = 0; K32[m * 9 + 6] = 0; K32[m * 9 + 7] = 0; K32[m * 9 + 8] = 0;
    }
#pragma unroll
    for (int d = 0; d < 10; d++)
        for (int i = tid; i < 512; i += 256) {
            float2 v = *(const float2*)(vb + d * SS + 2 * i);
            V32[d * 516 + i] = pkbf(v.y, v.x);
        }
    for (int d = 10; d < 16; d++)
        for (int i = tid; i < 516; i += 256) V32[d * 516 + i] = 0;

    // Q staging + rel tables (thread owns block-local query tid)
    float qv[10];
    {
        int n = qt * 256 + tid;
#pragma unroll
        for (int d = 0; d < 10; d++) qv[d] = qb[d * SS + n] * SCL;
#pragma unroll
        for (int d = 0; d < 10; d++) Qsm[tid * 18 + d] = __float2bfloat16(qv[d]);
        Q32[tid * 9 + 5] = 0; Q32[tid * 9 + 6] = 0; Q32[tid * 9 + 7] = 0; Q32[tid * 9 + 8] = 0;
    }
    __syncthreads();
    {
        int n = qt * 256 + tid;
        int x = n & 31, y = n >> 5;
        for (int t = 0; t < 32; t++) {
            const float* pw = srel + 630 + (t - x + 31) * 10;
            const float* ph = srel + (t - y + 31) * 10;
            float aw = 0.f, ah = 0.f;
#pragma unroll
            for (int d = 0; d < 10; d++) { aw += qv[d] * pw[d]; ah += qv[d] * ph[d]; }
            rw[tid * 34 + t] = aw;
            rh[tid * 34 + t] = ah;
        }
    }
    __syncthreads();

    int lane = tid & 31, wz = tid >> 5;
    int g = lane >> 2, t = lane & 3;
    uint32 qa[2][4];
#pragma unroll
    for (int mt = 0; mt < 2; mt++) {
        int r0 = wz * 32 + mt * 16;
        qa[mt][0] = Q32[(r0 + g) * 9 + t];
        qa[mt][1] = Q32[(r0 + g + 8) * 9 + t];
        qa[mt][2] = Q32[(r0 + g) * 9 + t + 4];
        qa[mt][3] = Q32[(r0 + g + 8) * 9 + t + 4];
    }
    float O[2][2][4];
    float s[4];
#pragma unroll
    for (int i = 0; i < 4; i++) {
        s[i] = 0.f;
        O[0][0][i] = 0.f; O[0][1][i] = 0.f; O[1][0][i] = 0.f; O[1][1][i] = 0.f;
    }

    for (int ch = 0; ch < 64; ch++) {
        int my = ch >> 1, mx0 = (ch & 1) << 4;
        int k0 = my * 32 + mx0;
        uint32 kb0[2], kb1[2], vb0[2], vb1[2];
        kb0[0] = K32[(k0 + g) * 9 + t];      kb0[1] = K32[(k0 + g) * 9 + t + 4];
        kb1[0] = K32[(k0 + 8 + g) * 9 + t];  kb1[1] = K32[(k0 + 8 + g) * 9 + t + 4];
        int kh = k0 >> 1;
        vb0[0] = V32[g * 516 + kh + t];        vb0[1] = V32[g * 516 + kh + t + 4];
        vb1[0] = V32[(g + 8) * 516 + kh + t];  vb1[1] = V32[(g + 8) * 516 + kh + t + 4];
#pragma unroll
        for (int mt = 0; mt < 2; mt++) {
            float c0[4] = {0.f, 0.f, 0.f, 0.f}, c1[4] = {0.f, 0.f, 0.f, 0.f};
            MMA16(c0, qa[mt], kb0);
            MMA16(c1, qa[mt], kb1);
            int r0 = wz * 32 + mt * 16 + g;
            float rh0 = rh[r0 * 34 + my], rh1 = rh[(r0 + 8) * 34 + my];
            float2 rw00 = *(float2*)&rw[r0 * 34 + mx0 + 2 * t];
            float2 rw01 = *(float2*)&rw[r0 * 34 + mx0 + 8 + 2 * t];
            float2 rw10 = *(float2*)&rw[(r0 + 8) * 34 + mx0 + 2 * t];
            float2 rw11 = *(float2*)&rw[(r0 + 8) * 34 + mx0 + 8 + 2 * t];
            float p00 = ex2f(c0[0] + rw00.x + rh0);
            float p01 = ex2f(c0[1] + rw00.y + rh0);
            float p02 = ex2f(c0[2] + rw10.x + rh1);
            float p03 = ex2f(c0[3] + rw10.y + rh1);
            float p10 = ex2f(c1[0] + rw01.x + rh0);
            float p11 = ex2f(c1[1] + rw01.y + rh0);
            float p12 = ex2f(c1[2] + rw11.x + rh1);
            float p13 = ex2f(c1[3] + rw11.y + rh1);
            s[mt * 2]     += (p00 + p01) + (p10 + p11);
            s[mt * 2 + 1] += (p02 + p03) + (p12 + p13);
            uint32 pa[4];
            pa[0] = pkbf(p01, p00);
            pa[1] = pkbf(p03, p02);
            pa[2] = pkbf(p11, p10);
            pa[3] = pkbf(p13, p12);
            MMA16(O[mt][0], pa, vb0);
            MMA16(O[mt][1], pa, vb1);
        }
    }
#pragma unroll
    for (int j = 0; j < 4; j++) {
        s[j] += __shfl_xor_sync(0xffffffffu, s[j], 1);
        s[j] += __shfl_xor_sync(0xffffffffu, s[j], 2);
        s[j] = 1.f / s[j];
    }
#pragma unroll
    for (int mt = 0; mt < 2; mt++) {
        int q0 = qt * 256 + wz * 32 + mt * 16 + g;
        float* op = g_attn + ((size_t)bh * 1024 + q0) * 10;
        float i0 = s[mt * 2], i1 = s[mt * 2 + 1];
        *(float2*)(op + 2 * t)      = make_float2(O[mt][0][0] * i0, O[mt][0][1] * i0);
        *(float2*)(op + 80 + 2 * t) = make_float2(O[mt][0][2] * i1, O[mt][0][3] * i1);
        if (t == 0) {
            *(float2*)(op + 8)      = make_float2(O[mt][1][0] * i0, O[mt][1][1] * i0);
            *(float2*)(op + 80 + 8) = make_float2(O[mt][1][2] * i1, O[mt][1][3] * i1);
        }
    }
}

// ---------------- pool: warp-per-channel partial ----------------
__global__ void __launch_bounds__(512) pool_partial_kernel() {
    int b = blockIdx.y;
    int c = blockIdx.x * 16 + (threadIdx.x >> 5);
    int lane = threadIdx.x & 31;
    const float* src = (c < CO) ? &g_conv[(b * CO + c) * SS]
                                : &g_attno[(b * 40 + c - CO) * SS];
    const float4* p = (const float4*)src;
    float s = 0.f;
#pragma unroll
    for (int i = 0; i < 8; i++) {
        float4 v = p[i * 32 + lane];
        s += (v.x + v.y) + (v.z + v.w);
    }
#pragma unroll
    for (int o = 16; o; o >>= 1) s += __shfl_xor_sync(0xffffffffu, s, o);
    if (lane == 0) g_pool[b * 128 + c] = s * (1.f / SS);
}

__global__ void fc_kernel(const float* __restrict__ fcw, const float* __restrict__ fcb,
                          float* __restrict__ out) {
    int b = blockIdx.x, tid = threadIdx.x;
    __shared__ float p[128];
    if (tid < 128) p[tid] = g_pool[b * 128 + tid];
    __syncthreads();
    if (tid < 100) {
        float a = fcb[tid];
#pragma unroll 4
        for (int c = 0; c < 128; c++) a += p[c] * fcw[tid * 128 + c];
        out[b * 100 + tid] = a;
    }
}

// ---------------- host ----------------
extern "C" void kernel_launch(void* const* d_in, const int* in_sizes, int n_in,
                              void* d_out, int out_size) {
    const float* x        = (const float*)d_in[0];
    const float* conv1_w  = (const float*)d_in[1];
    const float* conv1_b  = (const float*)d_in[2];
    const float* bn1_g    = (const float*)d_in[3];
    const float* bn1_b    = (const float*)d_in[4];
    const float* convo_w  = (const float*)d_in[5];
    const float* convo_b  = (const float*)d_in[6];
    const float* qkv_w    = (const float*)d_in[7];
    const float* qkv_b    = (const float*)d_in[8];
    const float* attno_w  = (const float*)d_in[9];
    const float* attno_b  = (const float*)d_in[10];
    const float* key_rel_h = (const float*)d_in[11];
    const float* key_rel_w = (const float*)d_in[12];
    const float* fc_w     = (const float*)d_in[13];
    const float* fc_b     = (const float*)d_in[14];
    float* out = (float*)d_out;

    static cudaStream_t s1 = nullptr;
    static cudaEvent_t evA = nullptr, evB = nullptr;
    if (!s1) {
        cudaStreamCreateWithFlags(&s1, cudaStreamNonBlocking);
        cudaEventCreateWithFlags(&evA, cudaEventDisableTiming);
        cudaEventCreateWithFlags(&evB, cudaEventDisableTiming);
    }

    const int CONVO_SMEM = (16 * 18 * 36) * 4 + 8 * 16 * 9 * 8;   // 50688
    cudaFuncSetAttribute(convo_kernel, cudaFuncAttributeMaxDynamicSharedMemorySize, CONVO_SMEM);
    cudaFuncSetAttribute(attn_kernel, cudaFuncAttributeMaxDynamicSharedMemorySize, ATTN_SMEM);

    float* d_h;    cudaGetSymbolAddress((void**)&d_h, g_h);
    float* d_qkv;  cudaGetSymbolAddress((void**)&d_qkv, g_qkv);
    float* d_attn; cudaGetSymbolAddress((void**)&d_attn, g_attn);
    float* d_attno; cudaGetSymbolAddress((void**)&d_attno, g_attno);

    conv1_kernel<<<dim3(C1, BB), 256>>>(x, conv1_w, conv1_b);
    bn_finalize_kernel<<<1, 64>>>(bn1_g, bn1_b);

    // fork: convo on side stream, attention branch on main stream
    cudaEventRecord(evA, 0);
    cudaStreamWaitEvent(s1, evA, 0);
    convo_kernel<<<dim3(11, BB, 2), 128, CONVO_SMEM, s1>>>(convo_w, convo_b);
    cudaEventRecord(evB, s1);

    conv1x1_kernel<<<dim3(15, BB, 2), 256>>>(d_h, qkv_w, qkv_b, d_qkv, 64, 120, 1);
    attn_kernel<<<dim3(4, 64), 256, ATTN_SMEM>>>(key_rel_h, key_rel_w);
    conv1x1_kernel<<<dim3(5, BB, 2), 256>>>(d_attn, attno_w, attno_b, d_attno, 40, 40, 0);

    // join before pooling
    cudaStreamWaitEvent(0, evB, 0);
    pool_partial_kernel<<<dim3(8, BB), 512>>>();
    fc_kernel<<<BB, 128>>>(fc_w, fc_b, out);
}

// round 7
// speedup vs baseline: 3.3608x; 1.6459x over previous
#include <cuda_runtime.h>
#include <cuda_bf16.h>

#define BB 16
#define SS 1024
#define C1 64
#define CO 88
#define DH 10
#define QSCALE 0.31622776601683794f
#define L2E 1.4426950408889634f
#define SCL (QSCALE * L2E)

typedef unsigned long long ull;
typedef unsigned int uint32;

__device__ __forceinline__ void fma2(ull& d, ull a, ull b) {
    asm("fma.rn.f32x2 %0, %1, %2, %0;" : "+l"(d) : "l"(a), "l"(b));
}
__device__ __forceinline__ ull pk(float a, float b) {
    ull r; asm("mov.b64 %0, {%1, %2};" : "=l"(r) : "f"(a), "f"(b)); return r;
}
__device__ __forceinline__ float2 up(ull v) {
    float2 r; asm("mov.b64 {%0, %1}, %2;" : "=f"(r.x), "=f"(r.y) : "l"(v)); return r;
}
__device__ __forceinline__ float ex2f(float x) {
    float r; asm("ex2.approx.ftz.f32 %0, %1;" : "=f"(r) : "f"(x)); return r;
}
__device__ __forceinline__ uint32 pkbf(float hi, float lo) {
    uint32 r; asm("cvt.rn.bf16x2.f32 %0, %1, %2;" : "=r"(r) : "f"(hi), "f"(lo)); return r;
}
__device__ __forceinline__ uint32 f2tf(float x) {
    uint32 r; asm("cvt.rna.tf32.f32 %0, %1;" : "=r"(r) : "f"(x)); return r;
}
#define MMA16(d, a, b) asm volatile( \
    "mma.sync.aligned.m16n8k16.row.col.f32.bf16.bf16.f32 " \
    "{%0,%1,%2,%3}, {%4,%5,%6,%7}, {%8,%9}, {%0,%1,%2,%3};\n" \
    : "+f"(d[0]), "+f"(d[1]), "+f"(d[2]), "+f"(d[3]) \
    : "r"(a[0]), "r"(a[1]), "r"(a[2]), "r"(a[3]), "r"(b[0]), "r"(b[1]))
#define MMAT(d, a, b) asm volatile( \
    "mma.sync.aligned.m16n8k8.row.col.f32.tf32.tf32.f32 " \
    "{%0,%1,%2,%3}, {%4,%5,%6,%7}, {%8,%9}, {%0,%1,%2,%3};\n" \
    : "+f"(d[0]), "+f"(d[1]), "+f"(d[2]), "+f"(d[3]) \
    : "r"(a[0]), "r"(a[1]), "r"(a[2]), "r"(a[3]), "r"(b[0]), "r"(b[1]))

// ---------------- scratch ----------------
__device__ float g_h[BB * C1 * SS];
__device__ float g_part[BB * C1 * 2];
__device__ float g_bn[2 * C1];
__device__ float g_conv[BB * CO * SS];
__device__ float g_qkv[BB * 120 * SS];
__device__ float g_attn[BB * 4 * SS * DH];
__device__ float g_attno[BB * 40 * SS];
__device__ float g_pool[BB * 128];
__device__ uint32 g_wco[4 * 9 * 88 * 16];   // tf32 bits: [icc][kk][oc][ic]
__device__ uint32 g_wq[120 * 64];           // tf32 bits: [oc][ic]

// ---------------- weight prep (tf32 transpose) ----------------
__global__ void w_prep_kernel(const float* __restrict__ convo_w,
                              const float* __restrict__ qkv_w) {
    int tid = blockIdx.x * blockDim.x + threadIdx.x;
    for (int i = tid; i < 4 * 9 * 88 * 16; i += gridDim.x * blockDim.x) {
        int ic16 = i & 15, r = i >> 4;
        int oc = r % 88; r /= 88;
        int kk = r % 9;  int icc = r / 9;
        g_wco[i] = f2tf(convo_w[(oc * 64 + icc * 16 + ic16) * 9 + kk]);
    }
    for (int i = tid; i < 120 * 64; i += gridDim.x * blockDim.x)
        g_wq[i] = f2tf(qkv_w[i]);
}

// ---------------- conv1 3->64 3x3 + BN partial stats ----------------
__global__ void conv1_kernel(const float* __restrict__ x, const float* __restrict__ w,
                             const float* __restrict__ bias) {
    int oc = blockIdx.x, b = blockIdx.y;
    __shared__ float xs[3 * 34 * 34];
    __shared__ float ws[27];
    __shared__ float sred[16];
    int tid = threadIdx.x;
    for (int i = tid; i < 3 * 1156; i += 256) {
        int ic = i / 1156, r = i % 1156;
        int y = r / 34 - 1, xx = r % 34 - 1;
        float v = 0.f;
        if ((unsigned)y < 32u && (unsigned)xx < 32u)
            v = x[(b * 3 + ic) * SS + y * 32 + xx];
        xs[i] = v;
    }
    if (tid < 27) ws[tid] = w[oc * 27 + tid];
    __syncthreads();
    float bb = bias[oc];
    float s = 0.f, s2 = 0.f;
    for (int p = tid; p < SS; p += 256) {
        int y = p >> 5, xx = p & 31;
        float acc = bb;
#pragma unroll
        for (int ic = 0; ic < 3; ic++)
#pragma unroll
            for (int ky = 0; ky < 3; ky++)
#pragma unroll
                for (int kx = 0; kx < 3; kx++)
                    acc += xs[ic * 1156 + (y + ky) * 34 + xx + kx] * ws[ic * 9 + ky * 3 + kx];
        g_h[(b * C1 + oc) * SS + p] = acc;
        s += acc; s2 += acc * acc;
    }
#pragma unroll
    for (int o = 16; o; o >>= 1) {
        s  += __shfl_xor_sync(0xffffffffu, s, o);
        s2 += __shfl_xor_sync(0xffffffffu, s2, o);
    }
    if ((tid & 31) == 0) { sred[tid >> 5] = s; sred[8 + (tid >> 5)] = s2; }
    __syncthreads();
    if (tid == 0) {
        float S = 0.f, S2 = 0.f;
        for (int i = 0; i < 8; i++) { S += sred[i]; S2 += sred[8 + i]; }
        g_part[(b * 64 + oc) * 2]     = S;
        g_part[(b * 64 + oc) * 2 + 1] = S2;
    }
}

__global__ void bn_finalize_kernel(const float* __restrict__ gma, const float* __restrict__ bet) {
    int c = threadIdx.x;
    if (c < 64) {
        float S = 0.f, S2 = 0.f;
        for (int b = 0; b < 16; b++) {
            S  += g_part[(b * 64 + c) * 2];
            S2 += g_part[(b * 64 + c) * 2 + 1];
        }
        float mu  = S * (1.f / 16384.f);
        float var = S2 * (1.f / 16384.f) - mu * mu;
        float istd = rsqrtf(var + 1e-5f);
        float sc = gma[c] * istd;
        g_bn[c] = sc;
        g_bn[64 + c] = bet[c] - mu * sc;
    }
}

// ---------------- convo: tf32 implicit-GEMM MMA ----------------
// grid (8 pxtiles, 16 b), 256 threads = 8 warps; warp w -> image row y0+(w>>1), m-tile (w&1).
// smem: xs [6*36][18] tf32, ws [9][88][18] tf32, bias
#define CONVO_SMEM (6 * 36 * 18 * 4 + 9 * 88 * 18 * 4 + 88 * 4)
__global__ void __launch_bounds__(256) convo_mma_kernel(const float* __restrict__ bias) {
    extern __shared__ char dyn[];
    uint32* xs = (uint32*)dyn;                        // [6*36][18]
    uint32* ws = xs + 6 * 36 * 18;                    // [9][88][18]
    float* bsm = (float*)(ws + 9 * 88 * 18);
    int pxt = blockIdx.x, b = blockIdx.y;
    int y0 = pxt * 4;
    int tid = threadIdx.x;
    int wz = tid >> 5, lane = tid & 31;
    int g = lane >> 2, t = lane & 3;
    int wrow = wz >> 1, mtx = (wz & 1) * 16;

    for (int i = tid; i < 88; i += 256) bsm[i] = bias[i];

    float acc[11][4];
#pragma unroll
    for (int n = 0; n < 11; n++)
#pragma unroll
        for (int j = 0; j < 4; j++) acc[n][j] = 0.f;

    for (int icc = 0; icc < 4; icc++) {
        __syncthreads();
        for (int i = tid; i < 3456; i += 256) {
            int ic = i / 216, rem = i % 216;
            int row = rem / 36, col = rem % 36;
            int iy = y0 - 1 + row, ix = col - 1;
            float v = 0.f;
            int icg = icc * 16 + ic;
            if ((unsigned)iy < 32u && (unsigned)ix < 32u) {
                v = g_h[(b * 64 + icg) * SS + iy * 32 + ix];
                v = fmaxf(v * g_bn[icg] + g_bn[64 + icg], 0.f);
            }
            xs[(row * 36 + col) * 18 + ic] = f2tf(v);
        }
        for (int i = tid; i < 9 * 88 * 16; i += 256) {
            int ic = i & 15, m = i >> 4;
            int oc = m % 88, kk = m / 88;
            ws[(kk * 88 + oc) * 18 + ic] = g_wco[icc * 9 * 88 * 16 + i];
        }
        __syncthreads();
#pragma unroll
        for (int kk = 0; kk < 9; kk++) {
            int ky = kk / 3, kx = kk % 3;
            const uint32* xrow = xs + ((wrow + ky) * 36 + mtx + kx) * 18;
            const uint32* wrow_p = ws + kk * 88 * 18;
#pragma unroll
            for (int j = 0; j < 2; j++) {
                uint32 a[4];
                a[0] = xrow[g * 18 + 8 * j + t];
                a[1] = xrow[(g + 8) * 18 + 8 * j + t];
                a[2] = xrow[g * 18 + 8 * j + t + 4];
                a[3] = xrow[(g + 8) * 18 + 8 * j + t + 4];
#pragma unroll
                for (int nt = 0; nt < 11; nt++) {
                    uint32 bfrag[2];
                    bfrag[0] = wrow_p[(nt * 8 + g) * 18 + 8 * j + t];
                    bfrag[1] = wrow_p[(nt * 8 + g) * 18 + 8 * j + t + 4];
                    MMAT(acc[nt], a, bfrag);
                }
            }
        }
    }
    int pxbase = (y0 + wrow) * 32 + mtx;
#pragma unroll
    for (int nt = 0; nt < 11; nt++) {
        int oc0 = nt * 8 + 2 * t;
        float b0 = bsm[oc0], b1 = bsm[oc0 + 1];
        float* o0 = g_conv + (size_t)(b * 88 + oc0) * SS + pxbase;
        float* o1 = o0 + SS;
        o0[g]     = acc[nt][0] + b0;
        o1[g]     = acc[nt][1] + b1;
        o0[g + 8] = acc[nt][2] + b0;
        o1[g + 8] = acc[nt][3] + b1;
    }
}

// ---------------- qkv 1x1: tf32 MMA GEMM ----------------
// grid (8 pxtiles, 16 b), 256 threads = 8 warps; warp w -> 16 px.
#define QKV_SMEM (128 * 68 * 4 + 120 * 68 * 4 + 120 * 4)
__global__ void __launch_bounds__(256) qkv_mma_kernel(const float* __restrict__ bias) {
    extern __shared__ char dyn[];
    uint32* As = (uint32*)dyn;                 // [128][68]
    uint32* wqs = As + 128 * 68;               // [120][68]
    float* bsm = (float*)(wqs + 120 * 68);
    int pxt = blockIdx.x, b = blockIdx.y;
    int p0 = pxt * 128;
    int tid = threadIdx.x;
    int wz = tid >> 5, lane = tid & 31;
    int g = lane >> 2, t = lane & 3;

    for (int i = tid; i < 120; i += 256) bsm[i] = bias[i];
    for (int i = tid; i < 120 * 64; i += 256) {
        int n = i >> 6, ic = i & 63;
        wqs[n * 68 + ic] = g_wq[i];
    }
    for (int i = tid; i < 128 * 64; i += 256) {
        int ic = i >> 7, px = i & 127;
        float v = g_h[(b * 64 + ic) * SS + p0 + px];
        v = fmaxf(v * g_bn[ic] + g_bn[64 + ic], 0.f);
        As[px * 68 + ic] = f2tf(v);
    }
    __syncthreads();

    float acc[15][4];
#pragma unroll
    for (int n = 0; n < 15; n++)
#pragma unroll
        for (int j = 0; j < 4; j++) acc[n][j] = 0.f;

#pragma unroll
    for (int kc = 0; kc < 8; kc++) {
        int ic0 = kc * 8;
        const uint32* ar = As + (wz * 16) * 68 + ic0;
        uint32 a[4];
        a[0] = ar[g * 68 + t];
        a[1] = ar[(g + 8) * 68 + t];
        a[2] = ar[g * 68 + t + 4];
        a[3] = ar[(g + 8) * 68 + t + 4];
#pragma unroll
        for (int nt = 0; nt < 15; nt++) {
            uint32 bfrag[2];
            bfrag[0] = wqs[(nt * 8 + g) * 68 + ic0 + t];
            bfrag[1] = wqs[(nt * 8 + g) * 68 + ic0 + t + 4];
            MMAT(acc[nt], a, bfrag);
        }
    }
    int pxb = p0 + wz * 16;
#pragma unroll
    for (int nt = 0; nt < 15; nt++) {
        int oc0 = nt * 8 + 2 * t;
        float b0 = bsm[oc0], b1 = bsm[oc0 + 1];
        float* o0 = g_qkv + (size_t)(b * 120 + oc0) * SS + pxb;
        float* o1 = o0 + SS;
        o0[g]     = acc[nt][0] + b0;
        o1[g]     = acc[nt][1] + b1;
        o0[g + 8] = acc[nt][2] + b0;
        o1[g + 8] = acc[nt][3] + b1;
    }
}

// ---------------- 1x1 conv scalar (attno) ----------------
__global__ void __launch_bounds__(256) conv1x1_kernel(
        const float* __restrict__ in, const float* __restrict__ w,
        const float* __restrict__ bias, float* __restrict__ out,
        int IC, int OC) {
    __shared__ ull ws[8 * 64];
    int b = blockIdx.y, oc0 = blockIdx.x * 8, half = blockIdx.z, tid = threadIdx.x;
    for (int i = tid; i < 8 * IC; i += 256) {
        int o = i / IC, ic = i % IC;
        float wv = w[(oc0 + o) * IC + ic];
        ws[o * 64 + ic] = pk(wv, wv);
    }
    __syncthreads();
    const float* ip = in + (size_t)b * IC * SS + half * 512 + tid * 2;
    ull acc[8];
#pragma unroll
    for (int o = 0; o < 8; o++) acc[o] = 0ull;
#pragma unroll 8
    for (int ic = 0; ic < IC; ic++) {
        float2 v = *(const float2*)(ip + ic * SS);
        ull xa = pk(v.x, v.y);
#pragma unroll
        for (int o = 0; o < 8; o++) fma2(acc[o], ws[o * 64 + ic], xa);
    }
#pragma unroll
    for (int o = 0; o < 8; o++) {
        float bb = bias[oc0 + o];
        float2 a = up(acc[o]);
        *(float2*)&out[(size_t)(b * OC + oc0 + o) * SS + half * 512 + tid * 2]
            = make_float2(a.x + bb, a.y + bb);
    }
}

// ---------------- fused attention: bf16 mma.sync flash-style ----------------
#define SM_K   0
#define SM_V   36864
#define SM_Q   (36864 + 33024)
#define SM_RW  (SM_Q + 9216)
#define SM_RH  (SM_RW + 34816)
#define SM_REL (SM_RH + 34816)
#define ATTN_SMEM (SM_REL + 5040)

__global__ void __launch_bounds__(256) attn_kernel(const float* __restrict__ relh,
                                                   const float* __restrict__ relw) {
    extern __shared__ char smem[];
    __nv_bfloat16* Ksm = (__nv_bfloat16*)(smem + SM_K);
    __nv_bfloat16* Qsm = (__nv_bfloat16*)(smem + SM_Q);
    uint32* K32 = (uint32*)(smem + SM_K);
    uint32* V32 = (uint32*)(smem + SM_V);
    uint32* Q32 = (uint32*)(smem + SM_Q);
    float* rw   = (float*)(smem + SM_RW);
    float* rh   = (float*)(smem + SM_RH);
    float* srel = (float*)(smem + SM_REL);

    int qt = blockIdx.x, bh = blockIdx.y;
    int b = bh >> 2, hh = bh & 3;
    const float* qb = g_qkv + (b * 120 + hh * 10) * SS;
    const float* kb = qb + 40 * SS;
    const float* vb = qb + 80 * SS;
    int tid = threadIdx.x;

    for (int i = tid; i < 1260; i += 256) srel[i] = (i < 630 ? relh[i] : relw[i - 630]);
#pragma unroll
    for (int d = 0; d < 10; d++)
        for (int m = tid; m < 1024; m += 256)
            Ksm[m * 18 + d] = __float2bfloat16(kb[d * SS + m]);
    for (int m = tid; m < 1024; m += 256) {
        K32[m * 9 + 5] = 0; K32[m * 9 + 6] = 0; K32[m * 9 + 7] = 0; K32[m * 9 + 8] = 0;
    }
#pragma unroll
    for (int d = 0; d < 10; d++)
        for (int i = tid; i < 512; i += 256) {
            float2 v = *(const float2*)(vb + d * SS + 2 * i);
            V32[d * 516 + i] = pkbf(v.y, v.x);
        }
    for (int d = 10; d < 16; d++)
        for (int i = tid; i < 516; i += 256) V32[d * 516 + i] = 0;

    float qv[10];
    {
        int n = qt * 256 + tid;
#pragma unroll
        for (int d = 0; d < 10; d++) qv[d] = qb[d * SS + n] * SCL;
#pragma unroll
        for (int d = 0; d < 10; d++) Qsm[tid * 18 + d] = __float2bfloat16(qv[d]);
        Q32[tid * 9 + 5] = 0; Q32[tid * 9 + 6] = 0; Q32[tid * 9 + 7] = 0; Q32[tid * 9 + 8] = 0;
    }
    __syncthreads();
    {
        int n = qt * 256 + tid;
        int x = n & 31, y = n >> 5;
        for (int t = 0; t < 32; t++) {
            const float* pw = srel + 630 + (t - x + 31) * 10;
            const float* ph = srel + (t - y + 31) * 10;
            float aw = 0.f, ah = 0.f;
#pragma unroll
            for (int d = 0; d < 10; d++) { aw += qv[d] * pw[d]; ah += qv[d] * ph[d]; }
            rw[tid * 34 + t] = aw;
            rh[tid * 34 + t] = ah;
        }
    }
    __syncthreads();

    int lane = tid & 31, wz = tid >> 5;
    int g = lane >> 2, t = lane & 3;
    uint32 qa[2][4];
#pragma unroll
    for (int mt = 0; mt < 2; mt++) {
        int r0 = wz * 32 + mt * 16;
        qa[mt][0] = Q32[(r0 + g) * 9 + t];
        qa[mt][1] = Q32[(r0 + g + 8) * 9 + t];
        qa[mt][2] = Q32[(r0 + g) * 9 + t + 4];
        qa[mt][3] = Q32[(r0 + g + 8) * 9 + t + 4];
    }
    float O[2][2][4];
    float s[4];
#pragma unroll
    for (int i = 0; i < 4; i++) {
        s[i] = 0.f;
        O[0][0][i] = 0.f; O[0][1][i] = 0.f; O[1][0][i] = 0.f; O[1][1][i] = 0.f;
    }

    for (int ch = 0; ch < 64; ch++) {
        int my = ch >> 1, mx0 = (ch & 1) << 4;
        int k0 = my * 32 + mx0;
        uint32 kb0[2], kb1[2], vb0[2], vb1[2];
        kb0[0] = K32[(k0 + g) * 9 + t];      kb0[1] = K32[(k0 + g) * 9 + t + 4];
        kb1[0] = K32[(k0 + 8 + g) * 9 + t];  kb1[1] = K32[(k0 + 8 + g) * 9 + t + 4];
        int kh = k0 >> 1;
        vb0[0] = V32[g * 516 + kh + t];        vb0[1] = V32[g * 516 + kh + t + 4];
        vb1[0] = V32[(g + 8) * 516 + kh + t];  vb1[1] = V32[(g + 8) * 516 + kh + t + 4];
#pragma unroll
        for (int mt = 0; mt < 2; mt++) {
            float c0[4] = {0.f, 0.f, 0.f, 0.f}, c1[4] = {0.f, 0.f, 0.f, 0.f};
            MMA16(c0, qa[mt], kb0);
            MMA16(c1, qa[mt], kb1);
            int r0 = wz * 32 + mt * 16 + g;
            float rh0 = rh[r0 * 34 + my], rh1 = rh[(r0 + 8) * 34 + my];
            float2 rw00 = *(float2*)&rw[r0 * 34 + mx0 + 2 * t];
            float2 rw01 = *(float2*)&rw[r0 * 34 + mx0 + 8 + 2 * t];
            float2 rw10 = *(float2*)&rw[(r0 + 8) * 34 + mx0 + 2 * t];
            float2 rw11 = *(float2*)&rw[(r0 + 8) * 34 + mx0 + 8 + 2 * t];
            float p00 = ex2f(c0[0] + rw00.x + rh0);
            float p01 = ex2f(c0[1] + rw00.y + rh0);
            float p02 = ex2f(c0[2] + rw10.x + rh1);
            float p03 = ex2f(c0[3] + rw10.y + rh1);
            float p10 = ex2f(c1[0] + rw01.x + rh0);
            float p11 = ex2f(c1[1] + rw01.y + rh0);
            float p12 = ex2f(c1[2] + rw11.x + rh1);
            float p13 = ex2f(c1[3] + rw11.y + rh1);
            s[mt * 2]     += (p00 + p01) + (p10 + p11);
            s[mt * 2 + 1] += (p02 + p03) + (p12 + p13);
            uint32 pa[4];
            pa[0] = pkbf(p01, p00);
            pa[1] = pkbf(p03, p02);
            pa[2] = pkbf(p11, p10);
            pa[3] = pkbf(p13, p12);
            MMA16(O[mt][0], pa, vb0);
            MMA16(O[mt][1], pa, vb1);
        }
    }
#pragma unroll
    for (int j = 0; j < 4; j++) {
        s[j] += __shfl_xor_sync(0xffffffffu, s[j], 1);
        s[j] += __shfl_xor_sync(0xffffffffu, s[j], 2);
        s[j] = 1.f / s[j];
    }
#pragma unroll
    for (int mt = 0; mt < 2; mt++) {
        int q0 = qt * 256 + wz * 32 + mt * 16 + g;
        float* op = g_attn + ((size_t)bh * 1024 + q0) * 10;
        float i0 = s[mt * 2], i1 = s[mt * 2 + 1];
        *(float2*)(op + 2 * t)      = make_float2(O[mt][0][0] * i0, O[mt][0][1] * i0);
        *(float2*)(op + 80 + 2 * t) = make_float2(O[mt][0][2] * i1, O[mt][0][3] * i1);
        if (t == 0) {
            *(float2*)(op + 8)      = make_float2(O[mt][1][0] * i0, O[mt][1][1] * i0);
            *(float2*)(op + 80 + 8) = make_float2(O[mt][1][2] * i1, O[mt][1][3] * i1);
        }
    }
}

// ---------------- pool + fc ----------------
__global__ void __launch_bounds__(512) pool_partial_kernel() {
    int b = blockIdx.y;
    int c = blockIdx.x * 16 + (threadIdx.x >> 5);
    int lane = threadIdx.x & 31;
    const float* src = (c < CO) ? &g_conv[(b * CO + c) * SS]
                                : &g_attno[(b * 40 + c - CO) * SS];
    const float4* p = (const float4*)src;
    float s = 0.f;
#pragma unroll
    for (int i = 0; i < 8; i++) {
        float4 v = p[i * 32 + lane];
        s += (v.x + v.y) + (v.z + v.w);
    }
#pragma unroll
    for (int o = 16; o; o >>= 1) s += __shfl_xor_sync(0xffffffffu, s, o);
    if (lane == 0) g_pool[b * 128 + c] = s * (1.f / SS);
}

__global__ void fc_kernel(const float* __restrict__ fcw, const float* __restrict__ fcb,
                          float* __restrict__ out) {
    int b = blockIdx.x, tid = threadIdx.x;
    __shared__ float p[128];
    if (tid < 128) p[tid] = g_pool[b * 128 + tid];
    __syncthreads();
    if (tid < 100) {
        float a = fcb[tid];
#pragma unroll 4
        for (int c = 0; c < 128; c++) a += p[c] * fcw[tid * 128 + c];
        out[b * 100 + tid] = a;
    }
}

// ---------------- host ----------------
extern "C" void kernel_launch(void* const* d_in, const int* in_sizes, int n_in,
                              void* d_out, int out_size) {
    const float* x        = (const float*)d_in[0];
    const float* conv1_w  = (const float*)d_in[1];
    const float* conv1_b  = (const float*)d_in[2];
    const float* bn1_g    = (const float*)d_in[3];
    const float* bn1_b    = (const float*)d_in[4];
    const float* convo_w  = (const float*)d_in[5];
    const float* convo_b  = (const float*)d_in[6];
    const float* qkv_w    = (const float*)d_in[7];
    const float* qkv_b    = (const float*)d_in[8];
    const float* attno_w  = (const float*)d_in[9];
    const float* attno_b  = (const float*)d_in[10];
    const float* key_rel_h = (const float*)d_in[11];
    const float* key_rel_w = (const float*)d_in[12];
    const float* fc_w     = (const float*)d_in[13];
    const float* fc_b     = (const float*)d_in[14];
    float* out = (float*)d_out;

    static cudaStream_t s1 = nullptr;
    static cudaEvent_t evA = nullptr, evB = nullptr;
    if (!s1) {
        cudaStreamCreateWithFlags(&s1, cudaStreamNonBlocking);
        cudaEventCreateWithFlags(&evA, cudaEventDisableTiming);
        cudaEventCreateWithFlags(&evB, cudaEventDisableTiming);
    }

    cudaFuncSetAttribute(attn_kernel, cudaFuncAttributeMaxDynamicSharedMemorySize, ATTN_SMEM);
    cudaFuncSetAttribute(convo_mma_kernel, cudaFuncAttributeMaxDynamicSharedMemorySize, CONVO_SMEM);
    cudaFuncSetAttribute(qkv_mma_kernel, cudaFuncAttributeMaxDynamicSharedMemorySize, QKV_SMEM);

    float* d_attn; cudaGetSymbolAddress((void**)&d_attn, g_attn);
    float* d_attno; cudaGetSymbolAddress((void**)&d_attno, g_attno);

    w_prep_kernel<<<48, 256>>>(convo_w, qkv_w);
    conv1_kernel<<<dim3(C1, BB), 256>>>(x, conv1_w, conv1_b);
    bn_finalize_kernel<<<1, 64>>>(bn1_g, bn1_b);

    cudaEventRecord(evA, 0);
    cudaStreamWaitEvent(s1, evA, 0);
    convo_mma_kernel<<<dim3(8, BB), 256, CONVO_SMEM, s1>>>(convo_b);
    cudaEventRecord(evB, s1);

    qkv_mma_kernel<<<dim3(8, BB), 256, QKV_SMEM>>>(qkv_b);
    attn_kernel<<<dim3(4, 64), 256, ATTN_SMEM>>>(key_rel_h, key_rel_w);
    conv1x1_kernel<<<dim3(5, BB, 2), 256>>>(d_attn, attno_w, attno_b, d_attno, 40, 40);

    cudaStreamWaitEvent(0, evB, 0);
    pool_partial_kernel<<<dim3(8, BB), 512>>>();
    fc_kernel<<<BB, 128>>>(fc_w, fc_b, out);
}

// round 9
// speedup vs baseline: 3.7711x; 1.1221x over previous
#include <cuda_runtime.h>
#include <cuda_bf16.h>

#define BB 16
#define SS 1024
#define CO 88
#define QSCALE 0.31622776601683794f
#define L2E 1.4426950408889634f
#define SCL (QSCALE * L2E)

typedef unsigned int uint32;

__device__ __forceinline__ float ex2f(float x) {
    float r; asm("ex2.approx.ftz.f32 %0, %1;" : "=f"(r) : "f"(x)); return r;
}
__device__ __forceinline__ uint32 pkbf(float hi, float lo) {
    uint32 r; asm("cvt.rn.bf16x2.f32 %0, %1, %2;" : "=r"(r) : "f"(hi), "f"(lo)); return r;
}
__device__ __forceinline__ uint32 f2tf(float x) {
    uint32 r; asm("cvt.rna.tf32.f32 %0, %1;" : "=r"(r) : "f"(x)); return r;
}
__device__ __forceinline__ float lo_bf(uint32 p) { return __uint_as_float(p << 16); }
__device__ __forceinline__ float hi_bf(uint32 p) { return __uint_as_float(p & 0xffff0000u); }
#define MMA16(d, a, b) asm volatile( \
    "mma.sync.aligned.m16n8k16.row.col.f32.bf16.bf16.f32 " \
    "{%0,%1,%2,%3}, {%4,%5,%6,%7}, {%8,%9}, {%0,%1,%2,%3};\n" \
    : "+f"(d[0]), "+f"(d[1]), "+f"(d[2]), "+f"(d[3]) \
    : "r"(a[0]), "r"(a[1]), "r"(a[2]), "r"(a[3]), "r"(b[0]), "r"(b[1]))
#define MMAT(d, a, b) asm volatile( \
    "mma.sync.aligned.m16n8k8.row.col.f32.tf32.tf32.f32 " \
    "{%0,%1,%2,%3}, {%4,%5,%6,%7}, {%8,%9}, {%0,%1,%2,%3};\n" \
    : "+f"(d[0]), "+f"(d[1]), "+f"(d[2]), "+f"(d[3]) \
    : "r"(a[0]), "r"(a[1]), "r"(a[2]), "r"(a[3]), "r"(b[0]), "r"(b[1]))

// ---------------- scratch ----------------
__device__ float g_h[BB * 64 * SS];
__device__ float g_part[BB * 64 * 2];
__device__ float g_conv[BB * CO * SS];
__device__ float g_qkv[BB * 120 * SS];
__device__ float g_attn[BB * 4 * SS * 10];
__device__ uint32 g_wco[4 * 9 * 88 * 16];   // tf32 bits: [icc][kk][oc][ic]
__device__ uint32 g_wq[120 * 64];           // tf32 bits: [oc][ic]

// ---------------- BN scale/shift recompute (inline per block) ----------------
__device__ __forceinline__ void bn_inline(float* bns, float* bnb,
                                          const float* __restrict__ gma,
                                          const float* __restrict__ bet, int tid) {
    if (tid < 64) {
        float S = 0.f, S2 = 0.f;
#pragma unroll
        for (int ib = 0; ib < 16; ib++) {
            S  += g_part[(ib * 64 + tid) * 2];
            S2 += g_part[(ib * 64 + tid) * 2 + 1];
        }
        float mu  = S * (1.f / 16384.f);
        float var = S2 * (1.f / 16384.f) - mu * mu;
        float sc = gma[tid] * rsqrtf(var + 1e-5f);
        bns[tid] = sc;
        bnb[tid] = bet[tid] - mu * sc;
    }
}

// ---------------- conv1 3->64 3x3 + BN partial stats + weight prep ----------------
__global__ void conv1_kernel(const float* __restrict__ x, const float* __restrict__ w,
                             const float* __restrict__ bias,
                             const float* __restrict__ convo_w,
                             const float* __restrict__ qkv_w) {
    int oc = blockIdx.x, b = blockIdx.y;
    __shared__ float xs[3 * 34 * 34];
    __shared__ float ws[27];
    __shared__ float sred[16];
    int tid = threadIdx.x;
    // fold weight prep into the 64 blocks with b==0
    if (b == 0) {
        int base = oc * 256 + tid;
        for (int i = base; i < 4 * 9 * 88 * 16; i += 16384) {
            int ic16 = i & 15, r = i >> 4;
            int occ = r % 88; r /= 88;
            int kk = r % 9;  int icc = r / 9;
            g_wco[i] = f2tf(convo_w[(occ * 64 + icc * 16 + ic16) * 9 + kk]);
        }
        for (int i = base; i < 120 * 64; i += 16384) g_wq[i] = f2tf(qkv_w[i]);
    }
    for (int i = tid; i < 3 * 1156; i += 256) {
        int ic = i / 1156, r = i % 1156;
        int y = r / 34 - 1, xx = r % 34 - 1;
        float v = 0.f;
        if ((unsigned)y < 32u && (unsigned)xx < 32u)
            v = x[(b * 3 + ic) * SS + y * 32 + xx];
        xs[i] = v;
    }
    if (tid < 27) ws[tid] = w[oc * 27 + tid];
    __syncthreads();
    float bb = bias[oc];
    float s = 0.f, s2 = 0.f;
    for (int p = tid; p < SS; p += 256) {
        int y = p >> 5, xx = p & 31;
        float acc = bb;
#pragma unroll
        for (int ic = 0; ic < 3; ic++)
#pragma unroll
            for (int ky = 0; ky < 3; ky++)
#pragma unroll
                for (int kx = 0; kx < 3; kx++)
                    acc += xs[ic * 1156 + (y + ky) * 34 + xx + kx] * ws[ic * 9 + ky * 3 + kx];
        g_h[(b * 64 + oc) * SS + p] = acc;
        s += acc; s2 += acc * acc;
    }
#pragma unroll
    for (int o = 16; o; o >>= 1) {
        s  += __shfl_xor_sync(0xffffffffu, s, o);
        s2 += __shfl_xor_sync(0xffffffffu, s2, o);
    }
    if ((tid & 31) == 0) { sred[tid >> 5] = s; sred[8 + (tid >> 5)] = s2; }
    __syncthreads();
    if (tid == 0) {
        float S = 0.f, S2 = 0.f;
        for (int i = 0; i < 8; i++) { S += sred[i]; S2 += sred[8 + i]; }
        g_part[(b * 64 + oc) * 2]     = S;
        g_part[(b * 64 + oc) * 2 + 1] = S2;
    }
}

// ---------------- convo: tf32 implicit-GEMM, oc-split (48 + 40) ----------------
#define CONVO_SMEM ((6 * 36 * 18 + 9 * 48 * 18 + 48) * 4)
template <int NT, int OCB>
__device__ __forceinline__ void convo_impl(const float* __restrict__ bias,
                                           const float* __restrict__ gma,
                                           const float* __restrict__ bet) {
    extern __shared__ uint32 dynu[];
    uint32* xs = dynu;                 // [6*36][18]
    uint32* ws = xs + 6 * 36 * 18;     // [9*48][18]
    float* bsm = (float*)(ws + 9 * 48 * 18);  // [NT*8]
    __shared__ float bns[64], bnb[64];
    int pxt = blockIdx.x, b = blockIdx.y;
    int y0 = pxt * 4;
    int tid = threadIdx.x;
    int wz = tid >> 5, lane = tid & 31;
    int g = lane >> 2, t = lane & 3;
    int wrow = wz >> 1, mtx = (wz & 1) * 16;

    bn_inline(bns, bnb, gma, bet, tid);
    if (tid < NT * 8) bsm[tid] = bias[OCB + tid];

    float acc[NT][4];
#pragma unroll
    for (int n = 0; n < NT; n++)
#pragma unroll
        for (int j = 0; j < 4; j++) acc[n][j] = 0.f;

    for (int icc = 0; icc < 4; icc++) {
        __syncthreads();
        for (int i = tid; i < 3456; i += 256) {
            int ic = i / 216, rem = i % 216;
            int row = rem / 36, col = rem % 36;
            int iy = y0 - 1 + row, ix = col - 1;
            float v = 0.f;
            int icg = icc * 16 + ic;
            if ((unsigned)iy < 32u && (unsigned)ix < 32u) {
                v = g_h[(b * 64 + icg) * SS + iy * 32 + ix];
                v = fmaxf(v * bns[icg] + bnb[icg], 0.f);
            }
            xs[(row * 36 + col) * 18 + ic] = f2tf(v);
        }
        for (int i = tid; i < 9 * NT * 8 * 16; i += 256) {
            int ic = i & 15, m = i >> 4;
            int ocl = m % (NT * 8), kk = m / (NT * 8);
            ws[(kk * 48 + ocl) * 18 + ic] = g_wco[((icc * 9 + kk) * 88 + OCB + ocl) * 16 + ic];
        }
        __syncthreads();
#pragma unroll
        for (int kk = 0; kk < 9; kk++) {
            int ky = kk / 3, kx = kk % 3;
            const uint32* xrow = xs + ((wrow + ky) * 36 + mtx + kx) * 18;
            const uint32* wrow_p = ws + kk * 48 * 18;
#pragma unroll
            for (int j = 0; j < 2; j++) {
                uint32 a[4];
                a[0] = xrow[g * 18 + 8 * j + t];
                a[1] = xrow[(g + 8) * 18 + 8 * j + t];
                a[2] = xrow[g * 18 + 8 * j + t + 4];
                a[3] = xrow[(g + 8) * 18 + 8 * j + t + 4];
#pragma unroll
                for (int nt = 0; nt < NT; nt++) {
                    uint32 bfrag[2];
                    bfrag[0] = wrow_p[(nt * 8 + g) * 18 + 8 * j + t];
                    bfrag[1] = wrow_p[(nt * 8 + g) * 18 + 8 * j + t + 4];
                    MMAT(acc[nt], a, bfrag);
                }
            }
        }
    }
    int pxbase = (y0 + wrow) * 32 + mtx;
#pragma unroll
    for (int nt = 0; nt < NT; nt++) {
        int oc0 = OCB + nt * 8 + 2 * t;
        float b0 = bsm[nt * 8 + 2 * t], b1 = bsm[nt * 8 + 2 * t + 1];
        float* o0 = g_conv + (size_t)(b * 88 + oc0) * SS + pxbase;
        float* o1 = o0 + SS;
        o0[g]     = acc[nt][0] + b0;
        o1[g]     = acc[nt][1] + b1;
        o0[g + 8] = acc[nt][2] + b0;
        o1[g + 8] = acc[nt][3] + b1;
    }
}

__global__ void __launch_bounds__(256) convo_mma_kernel(const float* __restrict__ bias,
                                                        const float* __restrict__ gma,
                                                        const float* __restrict__ bet) {
    if (blockIdx.z == 0) convo_impl<6, 0>(bias, gma, bet);
    else                 convo_impl<5, 48>(bias, gma, bet);
}

// ---------------- qkv 1x1: tf32 MMA GEMM ----------------
#define QKV_SMEM ((128 * 68 + 120 * 68 + 120) * 4)
__global__ void __launch_bounds__(256) qkv_mma_kernel(const float* __restrict__ bias,
                                                      const float* __restrict__ gma,
                                                      const float* __restrict__ bet) {
    extern __shared__ uint32 dynu[];
    uint32* As = dynu;                 // [128][68]
    uint32* wqs = As + 128 * 68;       // [120][68]
    float* bsm = (float*)(wqs + 120 * 68);
    __shared__ float bns[64], bnb[64];
    int pxt = blockIdx.x, b = blockIdx.y;
    int p0 = pxt * 128;
    int tid = threadIdx.x;
    int wz = tid >> 5, lane = tid & 31;
    int g = lane >> 2, t = lane & 3;

    bn_inline(bns, bnb, gma, bet, tid);
    for (int i = tid; i < 120; i += 256) bsm[i] = bias[i];
    for (int i = tid; i < 120 * 64; i += 256) {
        int n = i >> 6, ic = i & 63;
        wqs[n * 68 + ic] = g_wq[i];
    }
    __syncthreads();
    for (int i = tid; i < 128 * 64; i += 256) {
        int ic = i >> 7, px = i & 127;
        float v = g_h[(b * 64 + ic) * SS + p0 + px];
        v = fmaxf(v * bns[ic] + bnb[ic], 0.f);
        As[px * 68 + ic] = f2tf(v);
    }
    __syncthreads();

    float acc[15][4];
#pragma unroll
    for (int n = 0; n < 15; n++)
#pragma unroll
        for (int j = 0; j < 4; j++) acc[n][j] = 0.f;

#pragma unroll
    for (int kc = 0; kc < 8; kc++) {
        int ic0 = kc * 8;
        const uint32* ar = As + (wz * 16) * 68 + ic0;
        uint32 a[4];
        a[0] = ar[g * 68 + t];
        a[1] = ar[(g + 8) * 68 + t];
        a[2] = ar[g * 68 + t + 4];
        a[3] = ar[(g + 8) * 68 + t + 4];
#pragma unroll
        for (int nt = 0; nt < 15; nt++) {
            uint32 bfrag[2];
            bfrag[0] = wqs[(nt * 8 + g) * 68 + ic0 + t];
            bfrag[1] = wqs[(nt * 8 + g) * 68 + ic0 + t + 4];
            MMAT(acc[nt], a, bfrag);
        }
    }
    int pxb = p0 + wz * 16;
#pragma unroll
    for (int nt = 0; nt < 15; nt++) {
        int oc0 = nt * 8 + 2 * t;
        float b0 = bsm[oc0], b1 = bsm[oc0 + 1];
        float* o0 = g_qkv + (size_t)(b * 120 + oc0) * SS + pxb;
        float* o1 = o0 + SS;
        o0[g]     = acc[nt][0] + b0;
        o1[g]     = acc[nt][1] + b1;
        o0[g + 8] = acc[nt][2] + b0;
        o1[g + 8] = acc[nt][3] + b1;
    }
}

// ---------------- fused attention: bf16 mma flash-style, 112KB smem ----------------
#define SM_K   0                       // 1024*9 uint (bf16 rows stride 18)
#define SM_V   36864                   // 16*516 uint
#define SM_Q   69888                   // 256*8 uint (later: srel f32[1260])
#define SM_RW  78080                   // 256*17 uint (bf16x2 pairs)
#define SM_RH  95488                   // 256*33 bf16
#define ATTN_SMEM 112384

__global__ void __launch_bounds__(256) attn_kernel(const float* __restrict__ relh,
                                                   const float* __restrict__ relw) {
    extern __shared__ char smem[];
    __nv_bfloat16* Ksm = (__nv_bfloat16*)(smem + SM_K);   // [1024][18]
    __nv_bfloat16* Qsm = (__nv_bfloat16*)(smem + SM_Q);   // [256][16]
    uint32* K32 = (uint32*)(smem + SM_K);
    uint32* V32 = (uint32*)(smem + SM_V);                 // [16][516]
    uint32* Q32 = (uint32*)(smem + SM_Q);
    uint32* RWP = (uint32*)(smem + SM_RW);                // [256][17] bf16x2 pairs
    __nv_bfloat16* RH = (__nv_bfloat16*)(smem + SM_RH);   // [256][33]

    int qt = blockIdx.x, bh = blockIdx.y;
    int b = bh >> 2, hh = bh & 3;
    const float* qb = g_qkv + (b * 120 + hh * 10) * SS;
    const float* kb = qb + 40 * SS;
    const float* vb = qb + 80 * SS;
    int tid = threadIdx.x;
    int lane = tid & 31, wz = tid >> 5;
    int g = lane >> 2, t = lane & 3;

    // phase 1: stage K, V, Q; compute qv
#pragma unroll
    for (int d = 0; d < 10; d++)
        for (int m = tid; m < 1024; m += 256)
            Ksm[m * 18 + d] = __float2bfloat16(kb[d * SS + m]);
    for (int m = tid; m < 1024; m += 256) {
        K32[m * 9 + 5] = 0; K32[m * 9 + 6] = 0; K32[m * 9 + 7] = 0; K32[m * 9 + 8] = 0;
    }
#pragma unroll
    for (int d = 0; d < 10; d++)
        for (int i = tid; i < 512; i += 256) {
            float2 v = *(const float2*)(vb + d * SS + 2 * i);
            V32[d * 516 + i] = pkbf(v.y, v.x);
        }
    for (int d = 10; d < 16; d++)
        for (int i = tid; i < 516; i += 256) V32[d * 516 + i] = 0;
    float qv[10];
    {
        int n = qt * 256 + tid;
#pragma unroll
        for (int d = 0; d < 10; d++) {
            qv[d] = qb[d * SS + n] * SCL;
            Qsm[tid * 16 + d] = __float2bfloat16(qv[d]);
        }
        Q32[tid * 8 + 5] = 0; Q32[tid * 8 + 6] = 0; Q32[tid * 8 + 7] = 0;
    }
    __syncthreads();

    // phase 2: extract Q fragments
    uint32 qa[2][4];
#pragma unroll
    for (int mt = 0; mt < 2; mt++) {
        int r0 = wz * 32 + mt * 16;
        qa[mt][0] = Q32[(r0 + g) * 8 + t];
        qa[mt][1] = Q32[(r0 + g + 8) * 8 + t];
        qa[mt][2] = Q32[(r0 + g) * 8 + t + 4];
        qa[mt][3] = Q32[(r0 + g + 8) * 8 + t + 4];
    }
    __syncthreads();

    // phase 3: srel into dead Q region
    float* srel = (float*)(smem + SM_Q);
    for (int i = tid; i < 1260; i += 256) srel[i] = (i < 630 ? relh[i] : relw[i - 630]);
    __syncthreads();

    // phase 4: rel tables (bf16)
    {
        int n = qt * 256 + tid;
        int x = n & 31, y = n >> 5;
        float prev = 0.f;
        for (int t2 = 0; t2 < 32; t2++) {
            const float* pw = srel + 630 + (t2 - x + 31) * 10;
            const float* ph = srel + (t2 - y + 31) * 10;
            float aw = 0.f, ah = 0.f;
#pragma unroll
            for (int d = 0; d < 10; d++) { aw += qv[d] * pw[d]; ah += qv[d] * ph[d]; }
            RH[tid * 33 + t2] = __float2bfloat16(ah);
            if (t2 & 1) RWP[tid * 17 + (t2 >> 1)] = pkbf(aw, prev);
            else prev = aw;
        }
    }
    __syncthreads();

    // main loop
    float O[2][2][4];
    float s[4];
#pragma unroll
    for (int i = 0; i < 4; i++) {
        s[i] = 0.f;
        O[0][0][i] = 0.f; O[0][1][i] = 0.f; O[1][0][i] = 0.f; O[1][1][i] = 0.f;
    }

    for (int ch = 0; ch < 64; ch++) {
        int my = ch >> 1, mx0 = (ch & 1) << 4;
        int k0 = my * 32 + mx0;
        uint32 kb0[2], kb1[2], vb0[2], vb1[2];
        kb0[0] = K32[(k0 + g) * 9 + t];      kb0[1] = K32[(k0 + g) * 9 + t + 4];
        kb1[0] = K32[(k0 + 8 + g) * 9 + t];  kb1[1] = K32[(k0 + 8 + g) * 9 + t + 4];
        int kh = k0 >> 1;
        vb0[0] = V32[g * 516 + kh + t];        vb0[1] = V32[g * 516 + kh + t + 4];
        vb1[0] = V32[(g + 8) * 516 + kh + t];  vb1[1] = V32[(g + 8) * 516 + kh + t + 4];
        int pi0 = (mx0 >> 1) + t;
#pragma unroll
        for (int mt = 0; mt < 2; mt++) {
            float c0[4] = {0.f, 0.f, 0.f, 0.f}, c1[4] = {0.f, 0.f, 0.f, 0.f};
            MMA16(c0, qa[mt], kb0);
            MMA16(c1, qa[mt], kb1);
            int r0 = wz * 32 + mt * 16 + g;
            float rh0 = __uint_as_float(((uint32)*(const unsigned short*)&RH[r0 * 33 + my]) << 16);
            float rh1 = __uint_as_float(((uint32)*(const unsigned short*)&RH[(r0 + 8) * 33 + my]) << 16);
            uint32 pw00 = RWP[r0 * 17 + pi0];
            uint32 pw01 = RWP[r0 * 17 + pi0 + 4];
            uint32 pw10 = RWP[(r0 + 8) * 17 + pi0];
            uint32 pw11 = RWP[(r0 + 8) * 17 + pi0 + 4];
            float p00 = ex2f(c0[0] + lo_bf(pw00) + rh0);
            float p01 = ex2f(c0[1] + hi_bf(pw00) + rh0);
            float p02 = ex2f(c0[2] + lo_bf(pw10) + rh1);
            float p03 = ex2f(c0[3] + hi_bf(pw10) + rh1);
            float p10 = ex2f(c1[0] + lo_bf(pw01) + rh0);
            float p11 = ex2f(c1[1] + hi_bf(pw01) + rh0);
            float p12 = ex2f(c1[2] + lo_bf(pw11) + rh1);
            float p13 = ex2f(c1[3] + hi_bf(pw11) + rh1);
            s[mt * 2]     += (p00 + p01) + (p10 + p11);
            s[mt * 2 + 1] += (p02 + p03) + (p12 + p13);
            uint32 pa[4];
            pa[0] = pkbf(p01, p00);
            pa[1] = pkbf(p03, p02);
            pa[2] = pkbf(p11, p10);
            pa[3] = pkbf(p13, p12);
            MMA16(O[mt][0], pa, vb0);
            MMA16(O[mt][1], pa, vb1);
        }
    }
#pragma unroll
    for (int j = 0; j < 4; j++) {
        s[j] += __shfl_xor_sync(0xffffffffu, s[j], 1);
        s[j] += __shfl_xor_sync(0xffffffffu, s[j], 2);
        s[j] = 1.f / s[j];
    }
#pragma unroll
    for (int mt = 0; mt < 2; mt++) {
        int q0 = qt * 256 + wz * 32 + mt * 16 + g;
        float* op = g_attn + ((size_t)bh * 1024 + q0) * 10;
        float i0 = s[mt * 2], i1 = s[mt * 2 + 1];
        *(float2*)(op + 2 * t)      = make_float2(O[mt][0][0] * i0, O[mt][0][1] * i0);
        *(float2*)(op + 80 + 2 * t) = make_float2(O[mt][0][2] * i1, O[mt][0][3] * i1);
        if (t == 0) {
            *(float2*)(op + 8)      = make_float2(O[mt][1][0] * i0, O[mt][1][1] * i0);
            *(float2*)(op + 80 + 8) = make_float2(O[mt][1][2] * i1, O[mt][1][3] * i1);
        }
    }
}

// ---------------- pool + attno(on pooled) + fc, fused ----------------
__global__ void __launch_bounds__(512) poolfc_kernel(
        const float* __restrict__ attw, const float* __restrict__ attb,
        const float* __restrict__ fcw, const float* __restrict__ fcb,
        float* __restrict__ out) {
    int b = blockIdx.x;
    int tid = threadIdx.x;
    int warp = tid >> 5, lane = tid & 31;
    __shared__ float pooled[128];
    __shared__ float pA[40];
#pragma unroll
    for (int i = 0; i < 8; i++) {
        int c = warp * 8 + i;
        const float* src = (c < CO) ? g_conv + (size_t)(b * CO + c) * SS
                                    : g_attn + (size_t)b * 40960 + (c - CO) * SS;
        const float4* p = (const float4*)src;
        float s = 0.f;
#pragma unroll
        for (int j = 0; j < 8; j++) {
            float4 v = p[j * 32 + lane];
            s += (v.x + v.y) + (v.z + v.w);
        }
#pragma unroll
        for (int o = 16; o; o >>= 1) s += __shfl_xor_sync(0xffffffffu, s, o);
        if (lane == 0) {
            if (c < CO) pooled[c] = s * (1.f / SS);
            else        pA[c - CO] = s * (1.f / SS);
        }
    }
    __syncthreads();
    if (tid < 40) {
        float a = attb[tid];
#pragma unroll 8
        for (int ic = 0; ic < 40; ic++) a += attw[tid * 40 + ic] * pA[ic];
        pooled[CO + tid] = a;
    }
    __syncthreads();
    if (tid < 100) {
        float a = fcb[tid];
#pragma unroll 8
        for (int c = 0; c < 128; c++) a += pooled[c] * fcw[tid * 128 + c];
        out[b * 100 + tid] = a;
    }
}

// ---------------- host ----------------
extern "C" void kernel_launch(void* const* d_in, const int* in_sizes, int n_in,
                              void* d_out, int out_size) {
    const float* x        = (const float*)d_in[0];
    const float* conv1_w  = (const float*)d_in[1];
    const float* conv1_b  = (const float*)d_in[2];
    const float* bn1_g    = (const float*)d_in[3];
    const float* bn1_b    = (const float*)d_in[4];
    const float* convo_w  = (const float*)d_in[5];
    const float* convo_b  = (const float*)d_in[6];
    const float* qkv_w    = (const float*)d_in[7];
    const float* qkv_b    = (const float*)d_in[8];
    const float* attno_w  = (const float*)d_in[9];
    const float* attno_b  = (const float*)d_in[10];
    const float* key_rel_h = (const float*)d_in[11];
    const float* key_rel_w = (const float*)d_in[12];
    const float* fc_w     = (const float*)d_in[13];
    const float* fc_b     = (const float*)d_in[14];
    float* out = (float*)d_out;

    static cudaStream_t s1 = nullptr;
    static cudaEvent_t evA = nullptr, evB = nullptr;
    if (!s1) {
        cudaStreamCreateWithFlags(&s1, cudaStreamNonBlocking);
        cudaEventCreateWithFlags(&evA, cudaEventDisableTiming);
        cudaEventCreateWithFlags(&evB, cudaEventDisableTiming);
    }

    cudaFuncSetAttribute(attn_kernel, cudaFuncAttributeMaxDynamicSharedMemorySize, ATTN_SMEM);
    cudaFuncSetAttribute(convo_mma_kernel, cudaFuncAttributeMaxDynamicSharedMemorySize, CONVO_SMEM);
    cudaFuncSetAttribute(qkv_mma_kernel, cudaFuncAttributeMaxDynamicSharedMemorySize, QKV_SMEM);

    conv1_kernel<<<dim3(64, BB), 256>>>(x, conv1_w, conv1_b, convo_w, qkv_w);

    cudaEventRecord(evA, 0);
    cudaStreamWaitEvent(s1, evA, 0);
    convo_mma_kernel<<<dim3(8, BB, 2), 256, CONVO_SMEM, s1>>>(convo_b, bn1_g, bn1_b);
    cudaEventRecord(evB, s1);

    qkv_mma_kernel<<<dim3(8, BB), 256, QKV_SMEM>>>(qkv_b, bn1_g, bn1_b);
    attn_kernel<<<dim3(4, 64), 256, ATTN_SMEM>>>(key_rel_h, key_rel_w);

    cudaStreamWaitEvent(0, evB, 0);
    poolfc_kernel<<<BB, 512>>>(attno_w, attno_b, fc_w, fc_b, out);
}

// round 14
// speedup vs baseline: 4.1789x; 1.1081x over previous
#include <cuda_runtime.h>
#include <cuda_bf16.h>

#define BB 16
#define SS 1024
#define CO 88
#define QSCALE 0.31622776601683794f
#define L2E 1.4426950408889634f
#define SCL (QSCALE * L2E)

typedef unsigned int uint32;

__device__ __forceinline__ float ex2f(float x) {
    float r; asm("ex2.approx.ftz.f32 %0, %1;" : "=f"(r) : "f"(x)); return r;
}
__device__ __forceinline__ uint32 pkbf(float hi, float lo) {
    uint32 r; asm("cvt.rn.bf16x2.f32 %0, %1, %2;" : "=r"(r) : "f"(hi), "f"(lo)); return r;
}
__device__ __forceinline__ uint32 f2tf(float x) {
    uint32 r; asm("cvt.rna.tf32.f32 %0, %1;" : "=r"(r) : "f"(x)); return r;
}
__device__ __forceinline__ float lo_bf(uint32 p) { return __uint_as_float(p << 16); }
__device__ __forceinline__ float hi_bf(uint32 p) { return __uint_as_float(p & 0xffff0000u); }
#define MMA16(d, a, b) asm volatile( \
    "mma.sync.aligned.m16n8k16.row.col.f32.bf16.bf16.f32 " \
    "{%0,%1,%2,%3}, {%4,%5,%6,%7}, {%8,%9}, {%0,%1,%2,%3};\n" \
    : "+f"(d[0]), "+f"(d[1]), "+f"(d[2]), "+f"(d[3]) \
    : "r"(a[0]), "r"(a[1]), "r"(a[2]), "r"(a[3]), "r"(b[0]), "r"(b[1]))
#define MMAT(d, a, b) asm volatile( \
    "mma.sync.aligned.m16n8k8.row.col.f32.tf32.tf32.f32 " \
    "{%0,%1,%2,%3}, {%4,%5,%6,%7}, {%8,%9}, {%0,%1,%2,%3};\n" \
    : "+f"(d[0]), "+f"(d[1]), "+f"(d[2]), "+f"(d[3]) \
    : "r"(a[0]), "r"(a[1]), "r"(a[2]), "r"(a[3]), "r"(b[0]), "r"(b[1]))

// ---------------- scratch ----------------
__device__ float g_h[BB * 64 * SS];
__device__ float g_part[BB * 64 * 2];
__device__ float g_conv[BB * CO * SS];
__device__ float g_qkv[BB * 120 * SS];
__device__ float g_attn[BB * 4 * SS * 10];
__device__ uint32 g_wco[4 * 9 * 88 * 16];   // tf32 bits: [icc][kk][oc][ic]
__device__ uint32 g_wq[120 * 64];           // tf32 bits: [oc][ic]

// ---------------- BN scale/shift recompute (inline per block) ----------------
__device__ __forceinline__ void bn_inline(float* bns, float* bnb,
                                          const float* __restrict__ gma,
                                          const float* __restrict__ bet, int tid) {
    if (tid < 64) {
        float S = 0.f, S2 = 0.f;
#pragma unroll
        for (int ib = 0; ib < 16; ib++) {
            S  += g_part[(ib * 64 + tid) * 2];
            S2 += g_part[(ib * 64 + tid) * 2 + 1];
        }
        float mu  = S * (1.f / 16384.f);
        float var = S2 * (1.f / 16384.f) - mu * mu;
        float sc = gma[tid] * rsqrtf(var + 1e-5f);
        bns[tid] = sc;
        bnb[tid] = bet[tid] - mu * sc;
    }
}

// ---------------- conv1 3->64 3x3 + BN partial stats + weight prep ----------------
__global__ void conv1_kernel(const float* __restrict__ x, const float* __restrict__ w,
                             const float* __restrict__ bias,
                             const float* __restrict__ convo_w,
                             const float* __restrict__ qkv_w) {
    int oc = blockIdx.x, b = blockIdx.y;
    __shared__ float xs[3 * 34 * 34];
    __shared__ float ws[27];
    __shared__ float sred[16];
    int tid = threadIdx.x;
    if (b == 0) {
        int base = oc * 256 + tid;
        for (int i = base; i < 4 * 9 * 88 * 16; i += 16384) {
            int ic16 = i & 15, r = i >> 4;
            int occ = r % 88; r /= 88;
            int kk = r % 9;  int icc = r / 9;
            g_wco[i] = f2tf(convo_w[(occ * 64 + icc * 16 + ic16) * 9 + kk]);
        }
        for (int i = base; i < 120 * 64; i += 16384) g_wq[i] = f2tf(qkv_w[i]);
    }
    for (int i = tid; i < 3 * 1156; i += 256) {
        int ic = i / 1156, r = i % 1156;
        int y = r / 34 - 1, xx = r % 34 - 1;
        float v = 0.f;
        if ((unsigned)y < 32u && (unsigned)xx < 32u)
            v = x[(b * 3 + ic) * SS + y * 32 + xx];
        xs[i] = v;
    }
    if (tid < 27) ws[tid] = w[oc * 27 + tid];
    __syncthreads();
    float bb = bias[oc];
    float s = 0.f, s2 = 0.f;
    for (int p = tid; p < SS; p += 256) {
        int y = p >> 5, xx = p & 31;
        float acc = bb;
#pragma unroll
        for (int ic = 0; ic < 3; ic++)
#pragma unroll
            for (int ky = 0; ky < 3; ky++)
#pragma unroll
                for (int kx = 0; kx < 3; kx++)
                    acc += xs[ic * 1156 + (y + ky) * 34 + xx + kx] * ws[ic * 9 + ky * 3 + kx];
        g_h[(b * 64 + oc) * SS + p] = acc;
        s += acc; s2 += acc * acc;
    }
#pragma unroll
    for (int o = 16; o; o >>= 1) {
        s  += __shfl_xor_sync(0xffffffffu, s, o);
        s2 += __shfl_xor_sync(0xffffffffu, s2, o);
    }
    if ((tid & 31) == 0) { sred[tid >> 5] = s; sred[8 + (tid >> 5)] = s2; }
    __syncthreads();
    if (tid == 0) {
        float S = 0.f, S2 = 0.f;
        for (int i = 0; i < 8; i++) { S += sred[i]; S2 += sred[8 + i]; }
        g_part[(b * 64 + oc) * 2]     = S;
        g_part[(b * 64 + oc) * 2 + 1] = S2;
    }
}

// ---------------- convo: tf32 implicit-GEMM, oc-split (48 + 40) ----------------
#define CONVO_SMEM ((6 * 36 * 18 + 9 * 48 * 18 + 48) * 4)
template <int NT, int OCB>
__device__ __forceinline__ void convo_impl(const float* __restrict__ bias,
                                           const float* __restrict__ gma,
                                           const float* __restrict__ bet) {
    extern __shared__ uint32 dynu[];
    uint32* xs = dynu;                 // [6*36][18]
    uint32* ws = xs + 6 * 36 * 18;     // [9*48][18]
    float* bsm = (float*)(ws + 9 * 48 * 18);
    __shared__ float bns[64], bnb[64];
    int pxt = blockIdx.x, b = blockIdx.y;
    int y0 = pxt * 4;
    int tid = threadIdx.x;
    int wz = tid >> 5, lane = tid & 31;
    int g = lane >> 2, t = lane & 3;
    int wrow = wz >> 1, mtx = (wz & 1) * 16;

    bn_inline(bns, bnb, gma, bet, tid);
    if (tid < NT * 8) bsm[tid] = bias[OCB + tid];

    float acc[NT][4];
#pragma unroll
    for (int n = 0; n < NT; n++)
#pragma unroll
        for (int j = 0; j < 4; j++) acc[n][j] = 0.f;

    for (int icc = 0; icc < 4; icc++) {
        __syncthreads();
        for (int i = tid; i < 3456; i += 256) {
            int ic = i / 216, rem = i % 216;
            int row = rem / 36, col = rem % 36;
            int iy = y0 - 1 + row, ix = col - 1;
            float v = 0.f;
            int icg = icc * 16 + ic;
            if ((unsigned)iy < 32u && (unsigned)ix < 32u) {
                v = g_h[(b * 64 + icg) * SS + iy * 32 + ix];
                v = fmaxf(v * bns[icg] + bnb[icg], 0.f);
            }
            xs[(row * 36 + col) * 18 + ic] = f2tf(v);
        }
        for (int i = tid; i < 9 * NT * 8 * 16; i += 256) {
            int ic = i & 15, m = i >> 4;
            int ocl = m % (NT * 8), kk = m / (NT * 8);
            ws[(kk * 48 + ocl) * 18 + ic] = g_wco[((icc * 9 + kk) * 88 + OCB + ocl) * 16 + ic];
        }
        __syncthreads();
#pragma unroll
        for (int kk = 0; kk < 9; kk++) {
            int ky = kk / 3, kx = kk % 3;
            const uint32* xrow = xs + ((wrow + ky) * 36 + mtx + kx) * 18;
            const uint32* wrow_p = ws + kk * 48 * 18;
#pragma unroll
            for (int j = 0; j < 2; j++) {
                uint32 a[4];
                a[0] = xrow[g * 18 + 8 * j + t];
                a[1] = xrow[(g + 8) * 18 + 8 * j + t];
                a[2] = xrow[g * 18 + 8 * j + t + 4];
                a[3] = xrow[(g + 8) * 18 + 8 * j + t + 4];
#pragma unroll
                for (int nt = 0; nt < NT; nt++) {
                    uint32 bfrag[2];
                    bfrag[0] = wrow_p[(nt * 8 + g) * 18 + 8 * j + t];
                    bfrag[1] = wrow_p[(nt * 8 + g) * 18 + 8 * j + t + 4];
                    MMAT(acc[nt], a, bfrag);
                }
            }
        }
    }
    int pxbase = (y0 + wrow) * 32 + mtx;
#pragma unroll
    for (int nt = 0; nt < NT; nt++) {
        int oc0 = OCB + nt * 8 + 2 * t;
        float b0 = bsm[nt * 8 + 2 * t], b1 = bsm[nt * 8 + 2 * t + 1];
        float* o0 = g_conv + (size_t)(b * 88 + oc0) * SS + pxbase;
        float* o1 = o0 + SS;
        o0[g]     = acc[nt][0] + b0;
        o1[g]     = acc[nt][1] + b1;
        o0[g + 8] = acc[nt][2] + b0;
        o1[g + 8] = acc[nt][3] + b1;
    }
}

__global__ void __launch_bounds__(256) convo_mma_kernel(const float* __restrict__ bias,
                                                        const float* __restrict__ gma,
                                                        const float* __restrict__ bet) {
    if (blockIdx.z == 0) convo_impl<6, 0>(bias, gma, bet);
    else                 convo_impl<5, 48>(bias, gma, bet);
}

// ---------------- qkv 1x1: tf32 MMA GEMM ----------------
#define QKV_SMEM ((128 * 68 + 120 * 68 + 120) * 4)
__global__ void __launch_bounds__(256) qkv_mma_kernel(const float* __restrict__ bias,
                                                      const float* __restrict__ gma,
                                                      const float* __restrict__ bet) {
    extern __shared__ uint32 dynu[];
    uint32* As = dynu;                 // [128][68]
    uint32* wqs = As + 128 * 68;       // [120][68]
    float* bsm = (float*)(wqs + 120 * 68);
    __shared__ float bns[64], bnb[64];
    int pxt = blockIdx.x, b = blockIdx.y;
    int p0 = pxt * 128;
    int tid = threadIdx.x;
    int wz = tid >> 5, lane = tid & 31;
    int g = lane >> 2, t = lane & 3;

    bn_inline(bns, bnb, gma, bet, tid);
    for (int i = tid; i < 120; i += 256) bsm[i] = bias[i];
    for (int i = tid; i < 120 * 64; i += 256) {
        int n = i >> 6, ic = i & 63;
        wqs[n * 68 + ic] = g_wq[i];
    }
    __syncthreads();
    for (int i = tid; i < 128 * 64; i += 256) {
        int ic = i >> 7, px = i & 127;
        float v = g_h[(b * 64 + ic) * SS + p0 + px];
        v = fmaxf(v * bns[ic] + bnb[ic], 0.f);
        As[px * 68 + ic] = f2tf(v);
    }
    __syncthreads();

    float acc[15][4];
#pragma unroll
    for (int n = 0; n < 15; n++)
#pragma unroll
        for (int j = 0; j < 4; j++) acc[n][j] = 0.f;

#pragma unroll
    for (int kc = 0; kc < 8; kc++) {
        int ic0 = kc * 8;
        const uint32* ar = As + (wz * 16) * 68 + ic0;
        uint32 a[4];
        a[0] = ar[g * 68 + t];
        a[1] = ar[(g + 8) * 68 + t];
        a[2] = ar[g * 68 + t + 4];
        a[3] = ar[(g + 8) * 68 + t + 4];
#pragma unroll
        for (int nt = 0; nt < 15; nt++) {
            uint32 bfrag[2];
            bfrag[0] = wqs[(nt * 8 + g) * 68 + ic0 + t];
            bfrag[1] = wqs[(nt * 8 + g) * 68 + ic0 + t + 4];
            MMAT(acc[nt], a, bfrag);
        }
    }
    int pxb = p0 + wz * 16;
#pragma unroll
    for (int nt = 0; nt < 15; nt++) {
        int oc0 = nt * 8 + 2 * t;
        float b0 = bsm[oc0], b1 = bsm[oc0 + 1];
        float* o0 = g_qkv + (size_t)(b * 120 + oc0) * SS + pxb;
        float* o1 = o0 + SS;
        o0[g]     = acc[nt][0] + b0;
        o1[g]     = acc[nt][1] + b1;
        o0[g + 8] = acc[nt][2] + b0;
        o1[g + 8] = acc[nt][3] + b1;
    }
}

// ---------------- fused attention: bf16 mma flash-style, restructured ----------------
#define SM_K   0                       // 1024*9 uint (bf16 rows stride 18)
#define SM_V   36864                   // 16*516 uint
#define SM_Q   69888                   // 256*8 uint (later: srel f32[1260])
#define SM_RW  78080                   // 256*17 uint (bf16x2 pairs)
#define SM_RH  95488                   // 256*33 bf16
#define ATTN_SMEM 112384

__global__ void __launch_bounds__(256, 2) attn_kernel(const float* __restrict__ relh,
                                                      const float* __restrict__ relw) {
    extern __shared__ char smem[];
    __nv_bfloat16* Ksm = (__nv_bfloat16*)(smem + SM_K);   // [1024][18]
    __nv_bfloat16* Qsm = (__nv_bfloat16*)(smem + SM_Q);   // [256][16]
    uint32* K32 = (uint32*)(smem + SM_K);
    uint32* V32 = (uint32*)(smem + SM_V);                 // [16][516]
    uint32* Q32 = (uint32*)(smem + SM_Q);
    uint32* RWP = (uint32*)(smem + SM_RW);                // [256][17] bf16x2 pairs
    __nv_bfloat16* RH = (__nv_bfloat16*)(smem + SM_RH);   // [256][33]

    int qt = blockIdx.x, bh = blockIdx.y;
    int b = bh >> 2, hh = bh & 3;
    const float* qb = g_qkv + (b * 120 + hh * 10) * SS;
    const float* kb = qb + 40 * SS;
    const float* vb = qb + 80 * SS;
    int tid = threadIdx.x;
    int lane = tid & 31, wz = tid >> 5;
    int g = lane >> 2, t = lane & 3;

    // phase 1: stage K, V (row 10 = ones for softmax-sum), Q
#pragma unroll
    for (int d = 0; d < 10; d++)
        for (int m = tid; m < 1024; m += 256)
            Ksm[m * 18 + d] = __float2bfloat16(kb[d * SS + m]);
    for (int m = tid; m < 1024; m += 256) {
        K32[m * 9 + 5] = 0; K32[m * 9 + 6] = 0; K32[m * 9 + 7] = 0; K32[m * 9 + 8] = 0;
    }
#pragma unroll
    for (int d = 0; d < 10; d++)
        for (int i = tid; i < 512; i += 256) {
            float2 v = *(const float2*)(vb + d * SS + 2 * i);
            V32[d * 516 + i] = pkbf(v.y, v.x);
        }
    for (int i = tid; i < 516; i += 256) V32[10 * 516 + i] = 0x3F803F80u;  // ones row
    for (int d = 11; d < 16; d++)
        for (int i = tid; i < 516; i += 256) V32[d * 516 + i] = 0;
    float qv[10];
    {
        int n = qt * 256 + tid;
#pragma unroll
        for (int d = 0; d < 10; d++) {
            qv[d] = qb[d * SS + n] * SCL;
            Qsm[tid * 16 + d] = __float2bfloat16(qv[d]);
        }
        Q32[tid * 8 + 5] = 0; Q32[tid * 8 + 6] = 0; Q32[tid * 8 + 7] = 0;
    }
    __syncthreads();

    // phase 2: extract Q fragments
    uint32 qa[2][4];
#pragma unroll
    for (int mt = 0; mt < 2; mt++) {
        int r0 = wz * 32 + mt * 16;
        qa[mt][0] = Q32[(r0 + g) * 8 + t];
        qa[mt][1] = Q32[(r0 + g + 8) * 8 + t];
        qa[mt][2] = Q32[(r0 + g) * 8 + t + 4];
        qa[mt][3] = Q32[(r0 + g + 8) * 8 + t + 4];
    }
    __syncthreads();

    // phase 3: srel into dead Q region
    float* srel = (float*)(smem + SM_Q);
    for (int i = tid; i < 1260; i += 256) srel[i] = (i < 630 ? relh[i] : relw[i - 630]);
    __syncthreads();

    // phase 4: rel tables
    {
        int n = qt * 256 + tid;
        int x = n & 31, y = n >> 5;
        float prev = 0.f;
        for (int t2 = 0; t2 < 32; t2++) {
            const float* pw = srel + 630 + (t2 - x + 31) * 10;
            const float* ph = srel + (t2 - y + 31) * 10;
            float aw = 0.f, ah = 0.f;
#pragma unroll
            for (int d = 0; d < 10; d++) { aw += qv[d] * pw[d]; ah += qv[d] * ph[d]; }
            RH[tid * 33 + t2] = __float2bfloat16(ah);
            if (t2 & 1) RWP[tid * 17 + (t2 >> 1)] = pkbf(aw, prev);
            else prev = aw;
        }
    }
    __syncthreads();

    // phase 5: hoist rel-width logits into registers (8 values per mt/half)
    float rwv[2][2][8];
#pragma unroll
    for (int mt = 0; mt < 2; mt++) {
        int r0 = wz * 32 + mt * 16 + g;
#pragma unroll
        for (int hf = 0; hf < 2; hf++) {
            int pi = hf * 8 + t;
            uint32 a0 = RWP[r0 * 17 + pi],       a1 = RWP[r0 * 17 + pi + 4];
            uint32 b0 = RWP[(r0 + 8) * 17 + pi], b1 = RWP[(r0 + 8) * 17 + pi + 4];
            rwv[mt][hf][0] = lo_bf(a0); rwv[mt][hf][1] = hi_bf(a0);
            rwv[mt][hf][2] = lo_bf(a1); rwv[mt][hf][3] = hi_bf(a1);
            rwv[mt][hf][4] = lo_bf(b0); rwv[mt][hf][5] = hi_bf(b0);
            rwv[mt][hf][6] = lo_bf(b1); rwv[mt][hf][7] = hi_bf(b1);
        }
    }

    float O[2][2][4];
#pragma unroll
    for (int i = 0; i < 4; i++) {
        O[0][0][i] = 0.f; O[0][1][i] = 0.f; O[1][0][i] = 0.f; O[1][1][i] = 0.f;
    }

    for (int my = 0; my < 32; my++) {
        float rhv[2][2];
#pragma unroll
        for (int mt = 0; mt < 2; mt++) {
            int r0 = wz * 32 + mt * 16 + g;
            rhv[mt][0] = __uint_as_float(((uint32)*(const unsigned short*)&RH[r0 * 33 + my]) << 16);
            rhv[mt][1] = __uint_as_float(((uint32)*(const unsigned short*)&RH[(r0 + 8) * 33 + my]) << 16);
        }
#pragma unroll
        for (int hf = 0; hf < 2; hf++) {
            int k0 = my * 32 + hf * 16;
            uint32 kb0[2], kb1[2], vb0[2], vb1[2];
            kb0[0] = K32[(k0 + g) * 9 + t];      kb0[1] = K32[(k0 + g) * 9 + t + 4];
            kb1[0] = K32[(k0 + 8 + g) * 9 + t];  kb1[1] = K32[(k0 + 8 + g) * 9 + t + 4];
            int kh = k0 >> 1;
            vb0[0] = V32[g * 516 + kh + t];        vb0[1] = V32[g * 516 + kh + t + 4];
            vb1[0] = V32[(g + 8) * 516 + kh + t];  vb1[1] = V32[(g + 8) * 516 + kh + t + 4];
            float c[2][2][4];
#pragma unroll
            for (int mt = 0; mt < 2; mt++) {
#pragma unroll
                for (int j = 0; j < 4; j++) { c[mt][0][j] = 0.f; c[mt][1][j] = 0.f; }
                MMA16(c[mt][0], qa[mt], kb0);
                MMA16(c[mt][1], qa[mt], kb1);
            }
#pragma unroll
            for (int mt = 0; mt < 2; mt++) {
                const float* rw = rwv[mt][hf];
                float r0v = rhv[mt][0], r1v = rhv[mt][1];
                float p00 = ex2f(c[mt][0][0] + (rw[0] + r0v));
                float p01 = ex2f(c[mt][0][1] + (rw[1] + r0v));
                float p02 = ex2f(c[mt][0][2] + (rw[4] + r1v));
                float p03 = ex2f(c[mt][0][3] + (rw[5] + r1v));
                float p10 = ex2f(c[mt][1][0] + (rw[2] + r0v));
                float p11 = ex2f(c[mt][1][1] + (rw[3] + r0v));
                float p12 = ex2f(c[mt][1][2] + (rw[6] + r1v));
                float p13 = ex2f(c[mt][1][3] + (rw[7] + r1v));
                uint32 pa[4];
                pa[0] = pkbf(p01, p00);
                pa[1] = pkbf(p03, p02);
                pa[2] = pkbf(p11, p10);
                pa[3] = pkbf(p13, p12);
                MMA16(O[mt][0], pa, vb0);
                MMA16(O[mt][1], pa, vb1);
            }
        }
    }

    // epilogue: softmax sums live in V-ones column (col 10, t==1 lanes)
#pragma unroll
    for (int mt = 0; mt < 2; mt++) {
        int src = (lane & 28) | 1;
        float s0 = __shfl_sync(0xffffffffu, O[mt][1][0], src);
        float s1 = __shfl_sync(0xffffffffu, O[mt][1][2], src);
        float i0 = 1.f / s0, i1 = 1.f / s1;
        int q0 = qt * 256 + wz * 32 + mt * 16 + g;
        float* op = g_attn + ((size_t)bh * 1024 + q0) * 10;
        *(float2*)(op + 2 * t)      = make_float2(O[mt][0][0] * i0, O[mt][0][1] * i0);
        *(float2*)(op + 80 + 2 * t) = make_float2(O[mt][0][2] * i1, O[mt][0][3] * i1);
        if (t == 0) {
            *(float2*)(op + 8)      = make_float2(O[mt][1][0] * i0, O[mt][1][1] * i0);
            *(float2*)(op + 80 + 8) = make_float2(O[mt][1][2] * i1, O[mt][1][3] * i1);
        }
    }
}

// ---------------- pool + attno(on pooled) + fc, fused ----------------
__global__ void __launch_bounds__(512) poolfc_kernel(
        const float* __restrict__ attw, const float* __restrict__ attb,
        const float* __restrict__ fcw, const float* __restrict__ fcb,
        float* __restrict__ out) {
    int b = blockIdx.x;
    int tid = threadIdx.x;
    int warp = tid >> 5, lane = tid & 31;
    __shared__ float pooled[128];
    __shared__ float pA[40];
#pragma unroll
    for (int i = 0; i < 8; i++) {
        int c = warp * 8 + i;
        const float* src = (c < CO) ? g_conv + (size_t)(b * CO + c) * SS
                                    : g_attn + (size_t)b * 40960 + (c - CO) * SS;
        const float4* p = (const float4*)src;
        float s = 0.f;
#pragma unroll
        for (int j = 0; j < 8; j++) {
            float4 v = p[j * 32 + lane];
            s += (v.x + v.y) + (v.z + v.w);
        }
#pragma unroll
        for (int o = 16; o; o >>= 1) s += __shfl_xor_sync(0xffffffffu, s, o);
        if (lane == 0) {
            if (c < CO) pooled[c] = s * (1.f / SS);
            else        pA[c - CO] = s * (1.f / SS);
        }
    }
    __syncthreads();
    if (tid < 40) {
        float a = attb[tid];
#pragma unroll 8
        for (int ic = 0; ic < 40; ic++) a += attw[tid * 40 + ic] * pA[ic];
        pooled[CO + tid] = a;
    }
    __syncthreads();
    if (tid < 100) {
        float a = fcb[tid];
#pragma unroll 8
        for (int c = 0; c < 128; c++) a += pooled[c] * fcw[tid * 128 + c];
        out[b * 100 + tid] = a;
    }
}

// ---------------- host ----------------
extern "C" void kernel_launch(void* const* d_in, const int* in_sizes, int n_in,
                              void* d_out, int out_size) {
    const float* x        = (const float*)d_in[0];
    const float* conv1_w  = (const float*)d_in[1];
    const float* conv1_b  = (const float*)d_in[2];
    const float* bn1_g    = (const float*)d_in[3];
    const float* bn1_b    = (const float*)d_in[4];
    const float* convo_w  = (const float*)d_in[5];
    const float* convo_b  = (const float*)d_in[6];
    const float* qkv_w    = (const float*)d_in[7];
    const float* qkv_b    = (const float*)d_in[8];
    const float* attno_w  = (const float*)d_in[9];
    const float* attno_b  = (const float*)d_in[10];
    const float* key_rel_h = (const float*)d_in[11];
    const float* key_rel_w = (const float*)d_in[12];
    const float* fc_w     = (const float*)d_in[13];
    const float* fc_b     = (const float*)d_in[14];
    float* out = (float*)d_out;

    static cudaStream_t s1 = nullptr;
    static cudaEvent_t evA = nullptr, evB = nullptr;
    if (!s1) {
        cudaStreamCreateWithFlags(&s1, cudaStreamNonBlocking);
        cudaEventCreateWithFlags(&evA, cudaEventDisableTiming);
        cudaEventCreateWithFlags(&evB, cudaEventDisableTiming);
    }

    cudaFuncSetAttribute(attn_kernel, cudaFuncAttributeMaxDynamicSharedMemorySize, ATTN_SMEM);
    cudaFuncSetAttribute(convo_mma_kernel, cudaFuncAttributeMaxDynamicSharedMemorySize, CONVO_SMEM);
    cudaFuncSetAttribute(qkv_mma_kernel, cudaFuncAttributeMaxDynamicSharedMemorySize, QKV_SMEM);

    conv1_kernel<<<dim3(64, BB), 256>>>(x, conv1_w, conv1_b, convo_w, qkv_w);

    cudaEventRecord(evA, 0);
    cudaStreamWaitEvent(s1, evA, 0);
    convo_mma_kernel<<<dim3(8, BB, 2), 256, CONVO_SMEM, s1>>>(convo_b, bn1_g, bn1_b);
    cudaEventRecord(evB, s1);

    qkv_mma_kernel<<<dim3(8, BB), 256, QKV_SMEM>>>(qkv_b, bn1_g, bn1_b);
    attn_kernel<<<dim3(4, 64), 256, ATTN_SMEM>>>(key_rel_h, key_rel_w);

    cudaStreamWaitEvent(0, evB, 0);
    poolfc_kernel<<<BB, 512>>>(attno_w, attno_b, fc_w, fc_b, out);
}